// round 7
// baseline (speedup 1.0000x reference)
#include <cuda_runtime.h>
#include <cuda_fp16.h>
#include <math.h>
#include <stdint.h>

#define NN 32
#define LL 8192
#define CO 128
#define CI1 64
#define TT 10
#define LO 4096

// ---------------- scratch (__device__ globals; no allocation) ----------------
__device__ __align__(128) float g_y1[(size_t)NN * CO * LL];
__device__ __align__(128) float g_y2[(size_t)NN * CO * LL];
__device__ __align__(128) __half g_w1h[(size_t)NN * 5 * 1 * CO * 64];
__device__ __align__(128) __half g_w1l[(size_t)NN * 5 * 1 * CO * 64];
__device__ __align__(128) __half g_w2h[(size_t)NN * 5 * 2 * CO * 64];
__device__ __align__(128) __half g_w2l[(size_t)NN * 5 * 2 * CO * 64];
__device__ __align__(128) __half g_wdh[4 * CO * 64];
__device__ __align__(128) __half g_wdl[4 * CO * 64];
__device__ __align__(128) float g_xd[(size_t)NN * CO * LO];
__device__ float g_s1[NN * CO];
__device__ float g_s2[NN * CO];
__device__ float g_b1[CO];
__device__ float g_b2[CO];
__device__ float g_scale[NN * CO];
__device__ float g_shift[NN * CO];
__device__ float g_bscale[CO];
__device__ float g_bshift[CO];

// ---------------- small device helpers ----------------
__device__ __forceinline__ float mishf(float v) {
    float sp = (v > 20.f) ? v : log1pf(expf(v));
    return v * tanhf(sp);
}
__device__ __forceinline__ uint32_t smem_u32(const void* p) {
    uint32_t a;
    asm("{ .reg .u64 t; cvta.to.shared.u64 t, %1; cvt.u32.u64 %0, t; }" : "=r"(a) : "l"(p));
    return a;
}
__device__ __forceinline__ void cp16(uint32_t dst, const void* src) {
    asm volatile("cp.async.cg.shared.global [%0], [%1], 16;" :: "r"(dst), "l"(src));
}
__device__ __forceinline__ void cp_commit() {
    asm volatile("cp.async.commit_group;" ::: "memory");
}
template <int N>
__device__ __forceinline__ void cp_wait() {
    asm volatile("cp.async.wait_group %0;" :: "n"(N) : "memory");
}
__device__ __forceinline__ void ldsm4(uint32_t* r, uint32_t addr) {
    asm volatile("ldmatrix.sync.aligned.m8n8.x4.shared.b16 {%0,%1,%2,%3}, [%4];"
                 : "=r"(r[0]), "=r"(r[1]), "=r"(r[2]), "=r"(r[3]) : "r"(addr));
}
__device__ __forceinline__ void mma_f16(float* d, const uint32_t* a, const uint32_t* b) {
    asm volatile("mma.sync.aligned.m16n8k16.row.col.f32.f16.f16.f32 "
                 "{%0,%1,%2,%3}, {%4,%5,%6,%7}, {%8,%9}, {%0,%1,%2,%3};"
                 : "+f"(d[0]), "+f"(d[1]), "+f"(d[2]), "+f"(d[3])
                 : "r"(a[0]), "r"(a[1]), "r"(a[2]), "r"(a[3]), "r"(b[0]), "r"(b[1]));
}
__device__ __forceinline__ void h_split(float v, __half& h, __half& l) {
    h = __float2half_rn(v);
    l = __float2half_rn(v - __half2float(h));
}

// ============================================================================
// Conv-as-GEMM, warp-level fp16 MMA, 2-term W-split, fused stats, fused
// X-side transforms:
//   MODE 0: X source = raw fp32 (n,l,CI); convert to fp16 in loader.
//   MODE 1: X source = prev conv output y (n,o,LL) fp32; loader applies
//           instance-norm (scale/shift) + mish, transposes via staging smem.
//   MODE 2: MODE 1 + writes the transformed activation to skip_out (n,l,o)
//           fp32 (each l owned by exactly one CTA; coalesced along o).
// W pipeline: 3 smem buffers, prefetch distance 2, wait_group<1>.
// ============================================================================
template <int CI, int NSHIFT, int RS, int HALO, int NT, bool PER_N_STATS, int MODE>
__global__ void __launch_bounds__(512)
mma_conv(const float* __restrict__ Xsrc,
         const __half* __restrict__ Wh, const __half* __restrict__ Wl,
         float* __restrict__ Y, float* __restrict__ S1, float* __restrict__ S2,
         const float* __restrict__ scale, const float* __restrict__ shift,
         float* __restrict__ skip_out,
         size_t x_nstride, size_t w_nstride, int outL)
{
    constexpr int HF = CI / 64;
    constexpr int P = NSHIFT * HF;
    constexpr int XR = NT * RS + HALO;
    constexpr int XPITCH = CI * 2 + 16;      // bytes; row step ≡ 4 banks (mod 32)
    constexpr int WPITCH = 144;
    constexpr int WCH = 128 * WPITCH;
    constexpr int XT = XR * XPITCH;
    constexpr int NB = NT / 64;
    constexpr int NFR = 2 * NB;
    constexpr int STAGE_OFF = XT + 3 * 2 * WCH;

    extern __shared__ char sm[];
    const uint32_t base = smem_u32(sm);
    const uint32_t x_s = base;
    const uint32_t w_s = base + XT;

    const int tid = threadIdx.x;
    const int n = blockIdx.y;
    const int l0 = blockIdx.x * NT;

    // W prefetcher (one commit group per piece)
    auto load_w = [&](int piece, int buf) {
        const __half* ph = Wh + (size_t)n * w_nstride + (size_t)piece * 8192;
        const __half* pl = Wl + (size_t)n * w_nstride + (size_t)piece * 8192;
        uint32_t dst = w_s + (uint32_t)buf * (2 * WCH);
        for (int s = tid; s < 1024; s += 512) {
            int r = s >> 3, c = s & 7;
            cp16(dst + r * WPITCH + c * 16, ph + r * 64 + c * 8);
            cp16(dst + WCH + r * WPITCH + c * 16, pl + r * 64 + c * 8);
        }
        cp_commit();
    };
    load_w(0, 0);
    if (P > 1) load_w(1, 1);

    // ---------------- X tile fill ----------------
    if (MODE == 0) {
        const float* gx = Xsrc + (size_t)n * x_nstride;
        for (int s = tid; s < XR * (CI / 4); s += 512) {
            int r = s / (CI / 4), c = s % (CI / 4);
            long gl = (long)l0 - HALO + r;
            float4 v = make_float4(0.f, 0.f, 0.f, 0.f);
            if (gl >= 0) v = *(const float4*)(gx + gl * CI + c * 4);
            __half2 h0 = __floats2half2_rn(v.x, v.y);
            __half2 h1 = __floats2half2_rn(v.z, v.w);
            *(__half2*)(sm + r * XPITCH + c * 8) = h0;
            *(__half2*)(sm + r * XPITCH + c * 8 + 4) = h1;
        }
    } else {
        const float* yp = Xsrc + (size_t)n * CO * LL;
        float* stage = (float*)(sm + STAGE_OFF);     // [128][33] fp32
        const int o2 = tid & 127;
        const int lq = tid >> 7;                     // 0..3
        const float scv = scale[n * CO + o2];
        const float shv = shift[n * CO + o2];
        for (int chunk = 0; chunk < XR; chunk += 32) {
            {   // phase 1: coalesced along l into staging
                int lane = tid & 31, osub = tid >> 5;   // osub 0..15
                long glb = (long)l0 * RS - HALO + chunk + lane;
#pragma unroll
                for (int ob = 0; ob < 128; ob += 16) {
                    int o = ob + osub;
                    float v = 0.f;
                    if (glb >= 0 && chunk + lane < XR)
                        v = yp[(size_t)o * LL + glb];
                    stage[o * 33 + lane] = v;
                }
            }
            __syncthreads();
            {   // phase 2: transform + transpose into X smem (and skip_out)
#pragma unroll
                for (int ls = 0; ls < 32; ls += 4) {
                    int r = chunk + ls + lq;
                    if (r < XR) {
                        long gl = (long)l0 * RS - HALO + r;
                        float hv = 0.f;
                        if (gl >= 0) {
                            float v = stage[o2 * 33 + (ls + lq)];
                            hv = mishf(v * scv + shv);
                        }
                        *(__half*)(sm + r * XPITCH + o2 * 2) = __float2half_rn(hv);
                        if (MODE == 2)
                            skip_out[((size_t)n * LL + gl) * CO + o2] = hv;
                    }
                }
            }
            __syncthreads();
        }
    }

    const int warp = tid >> 5, lane = tid & 31;
    const int o0w = (warp >> 2) * 32, n0w = (warp & 3) * (NT / 4);
    const int a_row = (lane & 7) + ((lane >> 3) & 1) * 8;
    const int a_csh = (lane >> 4) * 8;
    const int b_jj = (lane & 7) + ((lane >> 4) << 3);
    const int b_csh = ((lane >> 3) & 1) * 8;

    float acc[2][NFR][4];
#pragma unroll
    for (int mi = 0; mi < 2; mi++)
#pragma unroll
        for (int nf = 0; nf < NFR; nf++)
#pragma unroll
            for (int q = 0; q < 4; q++) acc[mi][nf][q] = 0.f;

    for (int p = 0; p < P; p++) {
        if (p + 1 < P) cp_wait<1>(); else cp_wait<0>();
        __syncthreads();   // readers of buffer (p+2)%3 (= piece p-1) are done
        if (p + 2 < P) load_w(p + 2, (p + 2) % 3);

        const int k = p / HF, hf = p % HF;
        const uint32_t wh_b = w_s + (uint32_t)(p % 3) * (2 * WCH);
        const uint32_t wl_b = wh_b + WCH;

#pragma unroll
        for (int i16 = 0; i16 < 4; i16++) {
            const int i0 = i16 * 16;
            uint32_t Ah[2][4], Al[2][4];
#pragma unroll
            for (int mi = 0; mi < 2; mi++) {
                uint32_t ao = (uint32_t)((o0w + a_row + mi * 16) * WPITCH + (i0 + a_csh) * 2);
                ldsm4(Ah[mi], wh_b + ao);
                ldsm4(Al[mi], wl_b + ao);
            }
            const int xcol = (hf * 64 + i0 + b_csh) * 2;
#pragma unroll
            for (int nb = 0; nb < NB; nb++) {
                uint32_t B[4];
                uint32_t xo = (uint32_t)((RS * (n0w + nb * 16 + b_jj) + k) * XPITCH + xcol);
                ldsm4(B, x_s + xo);
#pragma unroll
                for (int mi = 0; mi < 2; mi++)
#pragma unroll
                    for (int hl = 0; hl < 2; hl++) {
                        float* d = acc[mi][nb * 2 + hl];
                        mma_f16(d, Ah[mi], &B[hl * 2]);
                        mma_f16(d, Al[mi], &B[hl * 2]);
                    }
            }
        }
    }

    // ---------------- epilogue: store + fused stats ----------------
    const int g = lane >> 2, tg = lane & 3;
#pragma unroll
    for (int mi = 0; mi < 2; mi++) {
        const int o = o0w + mi * 16 + g;
        float* row0 = Y + ((size_t)(n * CO + o)) * outL + l0 + n0w;
        float* row1 = row0 + (size_t)8 * outL;
#pragma unroll
        for (int nf = 0; nf < NFR; nf++) {
            int c = nf * 8 + tg * 2;
            *(float2*)(row0 + c) = make_float2(acc[mi][nf][0], acc[mi][nf][1]);
            *(float2*)(row1 + c) = make_float2(acc[mi][nf][2], acc[mi][nf][3]);
        }
    }
    float ts[4], tq[4];
#pragma unroll
    for (int r = 0; r < 4; r++) { ts[r] = 0.f; tq[r] = 0.f; }
#pragma unroll
    for (int mi = 0; mi < 2; mi++)
#pragma unroll
        for (int nf = 0; nf < NFR; nf++) {
            float a0 = acc[mi][nf][0], a1 = acc[mi][nf][1];
            float a2 = acc[mi][nf][2], a3 = acc[mi][nf][3];
            ts[2 * mi]     += a0 + a1;  tq[2 * mi]     += a0 * a0 + a1 * a1;
            ts[2 * mi + 1] += a2 + a3;  tq[2 * mi + 1] += a2 * a2 + a3 * a3;
        }
#pragma unroll
    for (int r = 0; r < 4; r++) {
        ts[r] += __shfl_xor_sync(0xffffffffu, ts[r], 1);
        ts[r] += __shfl_xor_sync(0xffffffffu, ts[r], 2);
        tq[r] += __shfl_xor_sync(0xffffffffu, tq[r], 1);
        tq[r] += __shfl_xor_sync(0xffffffffu, tq[r], 2);
    }
    if (tg == 0) {
        const int sbase = PER_N_STATS ? n * CO : 0;
#pragma unroll
        for (int r = 0; r < 4; r++) {
            int o = o0w + (r >> 1) * 16 + g + (r & 1) * 8;
            atomicAdd(&S1[sbase + o], ts[r]);
            atomicAdd(&S2[sbase + o], tq[r]);
        }
    }
}

// ---------------- gate + per-sample weights (fp16 hi/lo), parallel over i ----
__global__ void gate_weights_kernel(const float* __restrict__ t,
                                    const float* __restrict__ gw,
                                    const float* __restrict__ gb,
                                    const float* __restrict__ k5,
                                    const float* __restrict__ k3,
                                    const float* __restrict__ k1,
                                    const float* __restrict__ a3,
                                    const float* __restrict__ a5,
                                    __half* __restrict__ wh,
                                    __half* __restrict__ wl,
                                    float* __restrict__ S1, float* __restrict__ S2,
                                    int CI)
{
    int n = blockIdx.x;
    int o = threadIdx.x;
    int HF = CI >> 6;
    if (blockIdx.y == 0) {
        S1[n * CO + o] = 0.f;
        S2[n * CO + o] = 0.f;
    }
    float tv[TT];
#pragma unroll
    for (int j = 0; j < TT; j++) tv[j] = t[n * TT + j];
    float g[5];
    float mx = -1e30f;
#pragma unroll
    for (int e = 0; e < 5; e++) {
        float s = gb[e * CO + o];
        const float* gwr = gw + (size_t)(e * CO + o) * TT;
#pragma unroll
        for (int j = 0; j < TT; j++) s += tv[j] * gwr[j];
        g[e] = s;
        mx = fmaxf(mx, s);
    }
    float den = 0.f;
#pragma unroll
    for (int e = 0; e < 5; e++) { g[e] = expf(g[e] - mx); den += g[e]; }
    float inv = 1.f / den;
#pragma unroll
    for (int e = 0; e < 5; e++) g[e] *= inv;
    float g3 = g[3] * (1.f / 3.f);
    float g4 = g[4] * 0.2f;

    const int i_lo = blockIdx.y * 16, i_hi = i_lo + 16;
#pragma unroll 4
    for (int i = i_lo; i < i_hi; i++) {
        int oi = o * CI + i;
        const float* p5 = k5 + (size_t)oi * 5;
        const float* p3 = k3 + (size_t)oi * 3;
        float c1 = k1[oi], c3v = a3[oi], c5v = a5[oi];
        float bse = g4 * c5v;
        float wv[5];
        wv[0] = g[0] * p5[0] + bse;
        wv[1] = g[0] * p5[1] + bse;
        wv[2] = g[0] * p5[2] + g[1] * p3[0] + g3 * c3v + bse;
        wv[3] = g[0] * p5[3] + g[1] * p3[1] + g3 * c3v + bse;
        wv[4] = g[0] * p5[4] + g[1] * p3[2] + g3 * c3v + g[2] * c1 + bse;
        int hf = i >> 6, ii = i & 63;
#pragma unroll
        for (int k = 0; k < 5; k++) {
            __half h, l;
            h_split(wv[k], h, l);
            size_t idx = ((((size_t)n * 5 + k) * HF + hf) * 128 + o) * 64 + ii;
            wh[idx] = h;
            wl[idx] = l;
        }
    }
}

// ---------------- downsample weight reorder + split (+ zero bn accums) -------
__global__ void split_dw_kernel(const float* __restrict__ dw,
                                __half* __restrict__ wdh,
                                __half* __restrict__ wdl,
                                float* __restrict__ B1, float* __restrict__ B2)
{
    int idx = blockIdx.x * 256 + threadIdx.x;
    if (blockIdx.x == 0) {
        if (threadIdx.x < CO) B1[threadIdx.x] = 0.f;
        else B2[threadIdx.x - CO] = 0.f;
    }
    if (idx >= CO * 256) return;
    int o = idx >> 8, r = idx & 255;
    int kk = r >> 7, ifull = r & 127;
    float v = dw[(size_t)o * 256 + ifull * 2 + kk];
    __half h, l;
    h_split(v, h, l);
    size_t out = (((size_t)kk * 2 + (ifull >> 6)) * 128 + o) * 64 + (ifull & 63);
    wdh[out] = h;
    wdl[out] = l;
}

// ---------------- finalize kernels ----------------
__global__ void inorm_finalize(const float* __restrict__ S1, const float* __restrict__ S2,
                               const float* __restrict__ gamma, const float* __restrict__ beta,
                               float* __restrict__ scale, float* __restrict__ shift)
{
    int no = blockIdx.x * 256 + threadIdx.x;
    if (no >= NN * CO) return;
    int o = no & (CO - 1);
    float mu = S1[no] * (1.f / LL);
    float var = S2[no] * (1.f / LL) - mu * mu;
    float sc = gamma[o] * rsqrtf(var + 1e-5f);
    scale[no] = sc;
    shift[no] = beta[o] - mu * sc;
}

__global__ void bn_finalize(const float* __restrict__ B1, const float* __restrict__ B2,
                            const float* __restrict__ dg, const float* __restrict__ db,
                            float* __restrict__ bs, float* __restrict__ bb)
{
    int o = threadIdx.x;
    if (o >= CO) return;
    const float cnt = (float)NN * LO;
    float mu = B1[o] / cnt;
    float var = B2[o] / cnt - mu * mu;
    float sc = dg[o] * rsqrtf(var + 1e-5f);
    bs[o] = sc;
    bb[o] = db[o] - mu * sc;
}

// ---------------- batch-norm apply ----------------
__global__ void bn_apply_kernel(const float* __restrict__ xd,
                                const float* __restrict__ bs,
                                const float* __restrict__ bb,
                                float* __restrict__ out)
{
    size_t i4 = (size_t)blockIdx.x * 256 + threadIdx.x;
    const size_t total4 = (size_t)NN * CO * LO / 4;
    if (i4 >= total4) return;
    float4 v = ((const float4*)xd)[i4];
    int o = (int)((i4 * 4 / LO) & (CO - 1));
    float sc = bs[o], sh = bb[o];
    float4 r;
    r.x = mishf(v.x * sc + sh);
    r.y = mishf(v.y * sc + sh);
    r.z = mishf(v.z * sc + sh);
    r.w = mishf(v.w * sc + sh);
    ((float4*)out)[i4] = r;
}

// ---------------- launch ----------------
extern "C" void kernel_launch(void* const* d_in, const int* in_sizes, int n_in,
                              void* d_out, int out_size)
{
    const float* x        = (const float*)d_in[0];
    const float* t        = (const float*)d_in[1];
    const float* l1_k5    = (const float*)d_in[2];
    const float* l1_k3    = (const float*)d_in[3];
    const float* l1_k1    = (const float*)d_in[4];
    const float* l1_a3    = (const float*)d_in[5];
    const float* l1_a5    = (const float*)d_in[6];
    const float* l1_gw    = (const float*)d_in[7];
    const float* l1_gb    = (const float*)d_in[8];
    const float* l1_gamma = (const float*)d_in[9];
    const float* l1_beta  = (const float*)d_in[10];
    const float* l2_k5    = (const float*)d_in[11];
    const float* l2_k3    = (const float*)d_in[12];
    const float* l2_k1    = (const float*)d_in[13];
    const float* l2_a3    = (const float*)d_in[14];
    const float* l2_a5    = (const float*)d_in[15];
    const float* l2_gw    = (const float*)d_in[16];
    const float* l2_gb    = (const float*)d_in[17];
    const float* l2_gamma = (const float*)d_in[18];
    const float* l2_beta  = (const float*)d_in[19];
    const float* dw       = (const float*)d_in[20];
    const float* dg       = (const float*)d_in[21];
    const float* db       = (const float*)d_in[22];

    float* out      = (float*)d_out;
    float* out_xd   = out;
    float* out_skip = out + (size_t)NN * CO * LO;

    __half *w1h, *w1l, *w2h, *w2l, *wdh, *wdl;
    float *y1, *y2, *xdbuf, *scl, *shf, *bsc, *bsh, *s1, *s2, *b1, *b2;
    cudaGetSymbolAddress((void**)&y1, g_y1);
    cudaGetSymbolAddress((void**)&y2, g_y2);
    cudaGetSymbolAddress((void**)&w1h, g_w1h);
    cudaGetSymbolAddress((void**)&w1l, g_w1l);
    cudaGetSymbolAddress((void**)&w2h, g_w2h);
    cudaGetSymbolAddress((void**)&w2l, g_w2l);
    cudaGetSymbolAddress((void**)&wdh, g_wdh);
    cudaGetSymbolAddress((void**)&wdl, g_wdl);
    cudaGetSymbolAddress((void**)&xdbuf, g_xd);
    cudaGetSymbolAddress((void**)&scl, g_scale);
    cudaGetSymbolAddress((void**)&shf, g_shift);
    cudaGetSymbolAddress((void**)&bsc, g_bscale);
    cudaGetSymbolAddress((void**)&bsh, g_bshift);
    cudaGetSymbolAddress((void**)&s1, g_s1);
    cudaGetSymbolAddress((void**)&s2, g_s2);
    cudaGetSymbolAddress((void**)&b1, g_b1);
    cudaGetSymbolAddress((void**)&b2, g_b2);

    // smem: XT + 3*2*WCH (+ staging for MODE>=1)
    const int SM1 = 260 * 144 + 6 * 18432;                 // 148032
    const int SM2 = 260 * 272 + 6 * 18432 + 128 * 33 * 4;  // 198208
    const int SMD = 256 * 272 + 6 * 18432 + 128 * 33 * 4;  // 197120
    cudaFuncSetAttribute((const void*)mma_conv<64, 5, 1, 4, 256, true, 0>,
                         cudaFuncAttributeMaxDynamicSharedMemorySize, SM1);
    cudaFuncSetAttribute((const void*)mma_conv<128, 5, 1, 4, 256, true, 1>,
                         cudaFuncAttributeMaxDynamicSharedMemorySize, SM2);
    cudaFuncSetAttribute((const void*)mma_conv<128, 2, 2, 0, 128, false, 2>,
                         cudaFuncAttributeMaxDynamicSharedMemorySize, SMD);

    // layer 1 (reads raw x fp32)
    gate_weights_kernel<<<dim3(NN, CI1 / 16), 128>>>(t, l1_gw, l1_gb, l1_k5, l1_k3, l1_k1,
                                                     l1_a3, l1_a5, w1h, w1l, s1, s2, CI1);
    mma_conv<64, 5, 1, 4, 256, true, 0><<<dim3(LL / 256, NN), 512, SM1>>>(
        x, w1h, w1l, y1, s1, s2, nullptr, nullptr, nullptr,
        (size_t)LL * CI1, (size_t)5 * 1 * CO * 64, LL);
    inorm_finalize<<<(NN * CO + 255) / 256, 256>>>(s1, s2, l1_gamma, l1_beta, scl, shf);

    // layer 2 (loader applies norm+mish on y1)
    gate_weights_kernel<<<dim3(NN, CO / 16), 128>>>(t, l2_gw, l2_gb, l2_k5, l2_k3, l2_k1,
                                                    l2_a3, l2_a5, w2h, w2l, s1, s2, CO);
    mma_conv<128, 5, 1, 4, 256, true, 1><<<dim3(LL / 256, NN), 512, SM2>>>(
        y1, w2h, w2l, y2, s1, s2, scl, shf, nullptr,
        0, (size_t)5 * 2 * CO * 64, LL);
    inorm_finalize<<<(NN * CO + 255) / 256, 256>>>(s1, s2, l2_gamma, l2_beta, scl, shf);

    // downsample (loader applies norm+mish on y2 AND writes out_skip)
    split_dw_kernel<<<(CO * 256 + 255) / 256, 256>>>(dw, wdh, wdl, b1, b2);
    mma_conv<128, 2, 2, 0, 128, false, 2><<<dim3(LO / 128, NN), 512, SMD>>>(
        y2, wdh, wdl, xdbuf, b1, b2, scl, shf, out_skip,
        0, 0, LO);
    bn_finalize<<<1, 128>>>(b1, b2, dg, db, bsc, bsh);
    bn_apply_kernel<<<(int)(((size_t)NN * CO * LO / 4 + 255) / 256), 256>>>(xdbuf, bsc, bsh, out_xd);
}

// round 8
// speedup vs baseline: 1.3259x; 1.3259x over previous
#include <cuda_runtime.h>
#include <cuda_fp16.h>
#include <math.h>
#include <stdint.h>

#define NN 32
#define LL 8192
#define CO 128
#define CI1 64
#define TT 10
#define LO 4096

// ---------------- scratch (__device__ globals; no allocation) ----------------
__device__ __align__(128) __half g_xh[(size_t)NN * LL * CI1];
__device__ __align__(128) __half g_hh[(size_t)NN * LL * CO];
__device__ __align__(128) __half g_ssh[(size_t)NN * LL * CO];
__device__ __align__(128) float g_y[(size_t)NN * CO * LL];
__device__ __align__(128) __half g_w1h[(size_t)NN * 5 * 1 * CO * 64];
__device__ __align__(128) __half g_w1l[(size_t)NN * 5 * 1 * CO * 64];
__device__ __align__(128) __half g_w2h[(size_t)NN * 5 * 2 * CO * 64];
__device__ __align__(128) __half g_w2l[(size_t)NN * 5 * 2 * CO * 64];
__device__ __align__(128) __half g_wdh[4 * CO * 64];
__device__ __align__(128) __half g_wdl[4 * CO * 64];
__device__ __align__(128) float g_xd[(size_t)NN * CO * LO];
__device__ float g_s1[NN * CO];
__device__ float g_s2[NN * CO];
__device__ float g_b1[CO];
__device__ float g_b2[CO];
__device__ float g_scale[NN * CO];
__device__ float g_shift[NN * CO];
__device__ float g_bscale[CO];
__device__ float g_bshift[CO];

// ---------------- small device helpers ----------------
__device__ __forceinline__ float mishf(float v) {
    float sp = (v > 20.f) ? v : log1pf(expf(v));
    return v * tanhf(sp);
}
__device__ __forceinline__ uint32_t smem_u32(const void* p) {
    uint32_t a;
    asm("{ .reg .u64 t; cvta.to.shared.u64 t, %1; cvt.u32.u64 %0, t; }" : "=r"(a) : "l"(p));
    return a;
}
__device__ __forceinline__ void cp16(uint32_t dst, const void* src) {
    asm volatile("cp.async.cg.shared.global [%0], [%1], 16;" :: "r"(dst), "l"(src));
}
__device__ __forceinline__ void cp_commit() {
    asm volatile("cp.async.commit_group;" ::: "memory");
}
template <int N>
__device__ __forceinline__ void cp_wait() {
    asm volatile("cp.async.wait_group %0;" :: "n"(N) : "memory");
}
__device__ __forceinline__ void ldsm4(uint32_t* r, uint32_t addr) {
    asm volatile("ldmatrix.sync.aligned.m8n8.x4.shared.b16 {%0,%1,%2,%3}, [%4];"
                 : "=r"(r[0]), "=r"(r[1]), "=r"(r[2]), "=r"(r[3]) : "r"(addr));
}
__device__ __forceinline__ void mma_f16(float* d, const uint32_t* a, const uint32_t* b) {
    asm volatile("mma.sync.aligned.m16n8k16.row.col.f32.f16.f16.f32 "
                 "{%0,%1,%2,%3}, {%4,%5,%6,%7}, {%8,%9}, {%0,%1,%2,%3};"
                 : "+f"(d[0]), "+f"(d[1]), "+f"(d[2]), "+f"(d[3])
                 : "r"(a[0]), "r"(a[1]), "r"(a[2]), "r"(a[3]), "r"(b[0]), "r"(b[1]));
}
__device__ __forceinline__ void h_split(float v, __half& h, __half& l) {
    h = __float2half_rn(v);
    l = __float2half_rn(v - __half2float(h));
}

// ============================================================================
// Conv-as-GEMM, warp-level fp16 MMA, 2-term W-split (W = hi+lo fp16, X = fp16).
//   Y[n, o, l0+j] = sum_{k<NSHIFT, i<CI} W[n,o,i,k] * X[n, RS*(l0+j)+k-HALO, i]
// CTA 512 threads, tile M=128 (o) x NT (l). Per piece: wait -> barrier ->
// prefetch(p+1) -> MMA(p). Fused sum/sumsq stats in the epilogue.
// ============================================================================
template <int CI, int NSHIFT, int RS, int HALO, int NT, bool PER_N_STATS>
__global__ void __launch_bounds__(512)
mma_conv(const __half* __restrict__ X,
         const __half* __restrict__ Wh, const __half* __restrict__ Wl,
         float* __restrict__ Y, float* __restrict__ S1, float* __restrict__ S2,
         size_t x_nstride, size_t w_nstride, int outL)
{
    constexpr int HF = CI / 64;
    constexpr int P = NSHIFT * HF;
    constexpr int XR = NT * RS + HALO;
    constexpr int XPITCH = CI * 2 + 16;      // bytes; row step ≡ 4 banks (mod 32)
    constexpr int WPITCH = 144;
    constexpr int WCH = 128 * WPITCH;
    constexpr int XT = XR * XPITCH;
    constexpr int SEGR = CI / 8;
    constexpr int NB = NT / 64;
    constexpr int NFR = 2 * NB;

    extern __shared__ char sm[];
    const uint32_t base = smem_u32(sm);
    const uint32_t x_s = base;
    const uint32_t w_s = base + XT;

    const int tid = threadIdx.x;
    const int n = blockIdx.y;
    const int l0 = blockIdx.x * NT;

    if (HALO > 0 && blockIdx.x == 0) {
        const uint4 z = make_uint4(0, 0, 0, 0);
        for (int s = tid; s < HALO * SEGR; s += 512) {
            int r = s / SEGR, c = s % SEGR;
            *(uint4*)(sm + r * XPITCH + c * 16) = z;
        }
    }
    {   // X tile
        const __half* gx = X + (size_t)n * x_nstride;
        for (int s = tid; s < XR * SEGR; s += 512) {
            int r = s / SEGR, c = s % SEGR;
            long l = (long)l0 * RS - HALO + r;
            if (l >= 0)
                cp16(x_s + r * XPITCH + c * 16, gx + (size_t)l * CI + (size_t)c * 8);
        }
    }
    {   // W piece 0 (hi | lo)
        const __half* ph = Wh + (size_t)n * w_nstride;
        const __half* pl = Wl + (size_t)n * w_nstride;
        for (int s = tid; s < 1024; s += 512) {
            int r = s >> 3, c = s & 7;
            cp16(w_s + r * WPITCH + c * 16, ph + r * 64 + c * 8);
            cp16(w_s + WCH + r * WPITCH + c * 16, pl + r * 64 + c * 8);
        }
    }
    cp_commit();

    const int warp = tid >> 5, lane = tid & 31;
    const int o0w = (warp >> 2) * 32, n0w = (warp & 3) * (NT / 4);
    const int a_row = (lane & 7) + ((lane >> 3) & 1) * 8;
    const int a_csh = (lane >> 4) * 8;
    const int b_jj = (lane & 7) + ((lane >> 4) << 3);
    const int b_csh = ((lane >> 3) & 1) * 8;

    float acc[2][NFR][4];
#pragma unroll
    for (int mi = 0; mi < 2; mi++)
#pragma unroll
        for (int nf = 0; nf < NFR; nf++)
#pragma unroll
            for (int q = 0; q < 4; q++) acc[mi][nf][q] = 0.f;

    for (int p = 0; p < P; p++) {
        cp_wait<0>();
        __syncthreads();   // everyone done reading buffer (p+1)&1 (= piece p-1)
        if (p + 1 < P) {
            const int b = (p + 1) & 1;
            const __half* ph = Wh + (size_t)n * w_nstride + (size_t)(p + 1) * 8192;
            const __half* pl = Wl + (size_t)n * w_nstride + (size_t)(p + 1) * 8192;
            for (int s = tid; s < 1024; s += 512) {
                int r = s >> 3, c = s & 7;
                cp16(w_s + b * 2 * WCH + r * WPITCH + c * 16, ph + r * 64 + c * 8);
                cp16(w_s + b * 2 * WCH + WCH + r * WPITCH + c * 16, pl + r * 64 + c * 8);
            }
            cp_commit();
        }

        const int k = p / HF, hf = p % HF;
        const uint32_t wh_b = w_s + (uint32_t)(p & 1) * (2 * WCH);
        const uint32_t wl_b = wh_b + WCH;

#pragma unroll
        for (int i16 = 0; i16 < 4; i16++) {
            const int i0 = i16 * 16;
            uint32_t Ah[2][4], Al[2][4];
#pragma unroll
            for (int mi = 0; mi < 2; mi++) {
                uint32_t ao = (uint32_t)((o0w + a_row + mi * 16) * WPITCH + (i0 + a_csh) * 2);
                ldsm4(Ah[mi], wh_b + ao);
                ldsm4(Al[mi], wl_b + ao);
            }
            const int xcol = (hf * 64 + i0 + b_csh) * 2;
#pragma unroll
            for (int nb = 0; nb < NB; nb++) {
                uint32_t B[4];
                uint32_t xo = (uint32_t)((RS * (n0w + nb * 16 + b_jj) + k) * XPITCH + xcol);
                ldsm4(B, x_s + xo);
#pragma unroll
                for (int mi = 0; mi < 2; mi++)
#pragma unroll
                    for (int hl = 0; hl < 2; hl++) {
                        float* d = acc[mi][nb * 2 + hl];
                        mma_f16(d, Ah[mi], &B[hl * 2]);
                        mma_f16(d, Al[mi], &B[hl * 2]);
                    }
            }
        }
    }

    // ---------------- epilogue: store + fused stats ----------------
    const int g = lane >> 2, tg = lane & 3;
#pragma unroll
    for (int mi = 0; mi < 2; mi++) {
        const int o = o0w + mi * 16 + g;
        float* row0 = Y + ((size_t)(n * CO + o)) * outL + l0 + n0w;
        float* row1 = row0 + (size_t)8 * outL;
#pragma unroll
        for (int nf = 0; nf < NFR; nf++) {
            int c = nf * 8 + tg * 2;
            *(float2*)(row0 + c) = make_float2(acc[mi][nf][0], acc[mi][nf][1]);
            *(float2*)(row1 + c) = make_float2(acc[mi][nf][2], acc[mi][nf][3]);
        }
    }
    float ts[4], tq[4];
#pragma unroll
    for (int r = 0; r < 4; r++) { ts[r] = 0.f; tq[r] = 0.f; }
#pragma unroll
    for (int mi = 0; mi < 2; mi++)
#pragma unroll
        for (int nf = 0; nf < NFR; nf++) {
            float a0 = acc[mi][nf][0], a1 = acc[mi][nf][1];
            float a2 = acc[mi][nf][2], a3 = acc[mi][nf][3];
            ts[2 * mi]     += a0 + a1;  tq[2 * mi]     += a0 * a0 + a1 * a1;
            ts[2 * mi + 1] += a2 + a3;  tq[2 * mi + 1] += a2 * a2 + a3 * a3;
        }
#pragma unroll
    for (int r = 0; r < 4; r++) {
        ts[r] += __shfl_xor_sync(0xffffffffu, ts[r], 1);
        ts[r] += __shfl_xor_sync(0xffffffffu, ts[r], 2);
        tq[r] += __shfl_xor_sync(0xffffffffu, tq[r], 1);
        tq[r] += __shfl_xor_sync(0xffffffffu, tq[r], 2);
    }
    if (tg == 0) {
        const int sbase = PER_N_STATS ? n * CO : 0;
#pragma unroll
        for (int r = 0; r < 4; r++) {
            int o = o0w + (r >> 1) * 16 + g + (r & 1) * 8;
            atomicAdd(&S1[sbase + o], ts[r]);
            atomicAdd(&S2[sbase + o], tq[r]);
        }
    }
}

// ---------------- fp32 -> fp16 ----------------
__global__ void split_x_kernel(const float* __restrict__ src,
                               __half* __restrict__ hi, size_t count4)
{
    size_t i = (size_t)blockIdx.x * 256 + threadIdx.x;
    if (i >= count4) return;
    float4 v = ((const float4*)src)[i];
    ((__half2*)hi)[2 * i]     = __floats2half2_rn(v.x, v.y);
    ((__half2*)hi)[2 * i + 1] = __floats2half2_rn(v.z, v.w);
}

// ---------------- gate + per-sample weights (fp16 hi/lo) ----------------
// grid (NN, HF, 4), block 512 = 8 o-lanes x 64 ii-lanes. Gates in smem,
// coalesced W writes (ii contiguous), near-contiguous expert reads.
__global__ void __launch_bounds__(512)
gate_weights_kernel(const float* __restrict__ t,
                    const float* __restrict__ gw,
                    const float* __restrict__ gb,
                    const float* __restrict__ k5,
                    const float* __restrict__ k3,
                    const float* __restrict__ k1,
                    const float* __restrict__ a3,
                    const float* __restrict__ a5,
                    __half* __restrict__ wh,
                    __half* __restrict__ wl,
                    float* __restrict__ S1, float* __restrict__ S2,
                    int CI)
{
    const int n = blockIdx.x;
    const int hf = blockIdx.y;
    const int HF = gridDim.y;
    const int oc = blockIdx.z;           // o chunk: [oc*32, oc*32+32)
    const int tid = threadIdx.x;

    __shared__ float gs[5][128];
    if (tid < 128) {
        const int o = tid;
        if (blockIdx.y == 0 && blockIdx.z == 0) {
            S1[n * CO + o] = 0.f;
            S2[n * CO + o] = 0.f;
        }
        float tv[TT];
#pragma unroll
        for (int j = 0; j < TT; j++) tv[j] = t[n * TT + j];
        float g[5];
        float mx = -1e30f;
#pragma unroll
        for (int e = 0; e < 5; e++) {
            float s = gb[e * CO + o];
            const float* gwr = gw + (size_t)(e * CO + o) * TT;
#pragma unroll
            for (int j = 0; j < TT; j++) s += tv[j] * gwr[j];
            g[e] = s;
            mx = fmaxf(mx, s);
        }
        float den = 0.f;
#pragma unroll
        for (int e = 0; e < 5; e++) { g[e] = expf(g[e] - mx); den += g[e]; }
        float inv = 1.f / den;
        gs[0][o] = g[0] * inv;
        gs[1][o] = g[1] * inv;
        gs[2][o] = g[2] * inv;
        gs[3][o] = g[3] * inv * (1.f / 3.f);
        gs[4][o] = g[4] * inv * 0.2f;
    }
    __syncthreads();

    const int og = tid >> 6;             // 0..7
    const int ii = tid & 63;
    const int i = hf * 64 + ii;
    const size_t kstride = (size_t)HF * 128 * 64;

#pragma unroll
    for (int oj = 0; oj < 4; oj++) {
        const int o = oc * 32 + oj * 8 + og;
        const float g0 = gs[0][o], g1 = gs[1][o], g2 = gs[2][o];
        const float g3v = gs[3][o], g4v = gs[4][o];
        const int oi = o * CI + i;
        const float* p5 = k5 + (size_t)oi * 5;
        const float* p3 = k3 + (size_t)oi * 3;
        const float bse = g4v * a5[oi];
        const float c3v = g3v * a3[oi];
        float wv[5];
        wv[0] = g0 * p5[0] + bse;
        wv[1] = g0 * p5[1] + bse;
        wv[2] = g0 * p5[2] + g1 * p3[0] + c3v + bse;
        wv[3] = g0 * p5[3] + g1 * p3[1] + c3v + bse;
        wv[4] = g0 * p5[4] + g1 * p3[2] + c3v + g2 * k1[oi] + bse;
        const size_t idx0 = (((size_t)n * 5 * HF + hf) * 128 + o) * 64 + ii;
#pragma unroll
        for (int k = 0; k < 5; k++) {
            __half h, l;
            h_split(wv[k], h, l);
            wh[idx0 + k * kstride] = h;
            wl[idx0 + k * kstride] = l;
        }
    }
}

// ---------------- downsample weight reorder + split (+ zero bn accums) -------
__global__ void split_dw_kernel(const float* __restrict__ dw,
                                __half* __restrict__ wdh,
                                __half* __restrict__ wdl,
                                float* __restrict__ B1, float* __restrict__ B2)
{
    int idx = blockIdx.x * 256 + threadIdx.x;
    if (blockIdx.x == 0) {
        if (threadIdx.x < CO) B1[threadIdx.x] = 0.f;
        else B2[threadIdx.x - CO] = 0.f;
    }
    if (idx >= CO * 256) return;
    int o = idx >> 8, r = idx & 255;
    int kk = r >> 7, ifull = r & 127;
    float v = dw[(size_t)o * 256 + ifull * 2 + kk];
    __half h, l;
    h_split(v, h, l);
    size_t out = (((size_t)kk * 2 + (ifull >> 6)) * 128 + o) * 64 + (ifull & 63);
    wdh[out] = h;
    wdl[out] = l;
}

// ---------------- finalize kernels ----------------
__global__ void inorm_finalize(const float* __restrict__ S1, const float* __restrict__ S2,
                               const float* __restrict__ gamma, const float* __restrict__ beta,
                               float* __restrict__ scale, float* __restrict__ shift)
{
    int no = blockIdx.x * 256 + threadIdx.x;
    if (no >= NN * CO) return;
    int o = no & (CO - 1);
    float mu = S1[no] * (1.f / LL);
    float var = S2[no] * (1.f / LL) - mu * mu;
    float sc = gamma[o] * rsqrtf(var + 1e-5f);
    scale[no] = sc;
    shift[no] = beta[o] - mu * sc;
}

__global__ void bn_finalize(const float* __restrict__ B1, const float* __restrict__ B2,
                            const float* __restrict__ dg, const float* __restrict__ db,
                            float* __restrict__ bs, float* __restrict__ bb)
{
    int o = threadIdx.x;
    if (o >= CO) return;
    const float cnt = (float)NN * LO;
    float mu = B1[o] / cnt;
    float var = B2[o] / cnt - mu * mu;
    float sc = dg[o] * rsqrtf(var + 1e-5f);
    bs[o] = sc;
    bb[o] = db[o] - mu * sc;
}

// ---------------- norm + mish + transpose (fp16 out, optional fp32 out) ------
__global__ void norm_transpose_kernel(const float* __restrict__ y,
                                      const float* __restrict__ scale,
                                      const float* __restrict__ shift,
                                      float* __restrict__ out_full,
                                      __half* __restrict__ out_hi)
{
    __shared__ float tile[CO][33];
    __shared__ float sc[CO], sh[CO];
    int n = blockIdx.y, l0 = blockIdx.x * 32;
    int tid = threadIdx.x;
    if (tid < CO) { sc[tid] = scale[n * CO + tid]; sh[tid] = shift[n * CO + tid]; }
    __syncthreads();
    int lt = tid & 31, ob = tid >> 5;
#pragma unroll
    for (int r = 0; r < 16; r++) {
        int o = ob + 8 * r;
        float v = y[((size_t)(n * CO + o)) * LL + l0 + lt];
        tile[o][lt] = mishf(v * sc[o] + sh[o]);
    }
    __syncthreads();
    int oc = tid & 127, lb = tid >> 7;
#pragma unroll
    for (int ly = lb; ly < 32; ly += 2) {
        size_t idx = ((size_t)n * LL + l0 + ly) * CO + oc;
        float v = tile[oc][ly];
        if (out_full) out_full[idx] = v;
        out_hi[idx] = __float2half_rn(v);
    }
}

// ---------------- batch-norm apply ----------------
__global__ void bn_apply_kernel(const float* __restrict__ xd,
                                const float* __restrict__ bs,
                                const float* __restrict__ bb,
                                float* __restrict__ out)
{
    size_t i4 = (size_t)blockIdx.x * 256 + threadIdx.x;
    const size_t total4 = (size_t)NN * CO * LO / 4;
    if (i4 >= total4) return;
    float4 v = ((const float4*)xd)[i4];
    int o = (int)((i4 * 4 / LO) & (CO - 1));
    float sc = bs[o], sh = bb[o];
    float4 r;
    r.x = mishf(v.x * sc + sh);
    r.y = mishf(v.y * sc + sh);
    r.z = mishf(v.z * sc + sh);
    r.w = mishf(v.w * sc + sh);
    ((float4*)out)[i4] = r;
}

// ---------------- launch ----------------
extern "C" void kernel_launch(void* const* d_in, const int* in_sizes, int n_in,
                              void* d_out, int out_size)
{
    const float* x        = (const float*)d_in[0];
    const float* t        = (const float*)d_in[1];
    const float* l1_k5    = (const float*)d_in[2];
    const float* l1_k3    = (const float*)d_in[3];
    const float* l1_k1    = (const float*)d_in[4];
    const float* l1_a3    = (const float*)d_in[5];
    const float* l1_a5    = (const float*)d_in[6];
    const float* l1_gw    = (const float*)d_in[7];
    const float* l1_gb    = (const float*)d_in[8];
    const float* l1_gamma = (const float*)d_in[9];
    const float* l1_beta  = (const float*)d_in[10];
    const float* l2_k5    = (const float*)d_in[11];
    const float* l2_k3    = (const float*)d_in[12];
    const float* l2_k1    = (const float*)d_in[13];
    const float* l2_a3    = (const float*)d_in[14];
    const float* l2_a5    = (const float*)d_in[15];
    const float* l2_gw    = (const float*)d_in[16];
    const float* l2_gb    = (const float*)d_in[17];
    const float* l2_gamma = (const float*)d_in[18];
    const float* l2_beta  = (const float*)d_in[19];
    const float* dw       = (const float*)d_in[20];
    const float* dg       = (const float*)d_in[21];
    const float* db       = (const float*)d_in[22];

    float* out      = (float*)d_out;
    float* out_xd   = out;
    float* out_skip = out + (size_t)NN * CO * LO;

    __half *xh, *hh, *ssh, *w1h, *w1l, *w2h, *w2l, *wdh, *wdl;
    float *ybuf, *xdbuf, *scl, *shf, *bsc, *bsh, *s1, *s2, *b1, *b2;
    cudaGetSymbolAddress((void**)&xh, g_xh);
    cudaGetSymbolAddress((void**)&hh, g_hh);
    cudaGetSymbolAddress((void**)&ssh, g_ssh);
    cudaGetSymbolAddress((void**)&ybuf, g_y);
    cudaGetSymbolAddress((void**)&w1h, g_w1h);
    cudaGetSymbolAddress((void**)&w1l, g_w1l);
    cudaGetSymbolAddress((void**)&w2h, g_w2h);
    cudaGetSymbolAddress((void**)&w2l, g_w2l);
    cudaGetSymbolAddress((void**)&wdh, g_wdh);
    cudaGetSymbolAddress((void**)&wdl, g_wdl);
    cudaGetSymbolAddress((void**)&xdbuf, g_xd);
    cudaGetSymbolAddress((void**)&scl, g_scale);
    cudaGetSymbolAddress((void**)&shf, g_shift);
    cudaGetSymbolAddress((void**)&bsc, g_bscale);
    cudaGetSymbolAddress((void**)&bsh, g_bshift);
    cudaGetSymbolAddress((void**)&s1, g_s1);
    cudaGetSymbolAddress((void**)&s2, g_s2);
    cudaGetSymbolAddress((void**)&b1, g_b1);
    cudaGetSymbolAddress((void**)&b2, g_b2);

    // smem sizes: XT + 4 * (128*144)
    const int SM1 = 260 * 144 + 4 * 18432;   // 111168
    const int SM2 = 260 * 272 + 4 * 18432;   // 144448
    const int SMD = 256 * 272 + 4 * 18432;   // 143360
    cudaFuncSetAttribute((const void*)mma_conv<64, 5, 1, 4, 256, true>,
                         cudaFuncAttributeMaxDynamicSharedMemorySize, SM1);
    cudaFuncSetAttribute((const void*)mma_conv<128, 5, 1, 4, 256, true>,
                         cudaFuncAttributeMaxDynamicSharedMemorySize, SM2);
    cudaFuncSetAttribute((const void*)mma_conv<128, 2, 2, 0, 128, false>,
                         cudaFuncAttributeMaxDynamicSharedMemorySize, SMD);

    // x -> fp16
    {
        size_t c4 = (size_t)NN * LL * CI1 / 4;
        split_x_kernel<<<(int)((c4 + 255) / 256), 256>>>(x, xh, c4);
    }

    // layer 1
    gate_weights_kernel<<<dim3(NN, CI1 / 64, 4), 512>>>(t, l1_gw, l1_gb, l1_k5, l1_k3, l1_k1,
                                                        l1_a3, l1_a5, w1h, w1l, s1, s2, CI1);
    mma_conv<64, 5, 1, 4, 256, true><<<dim3(LL / 256, NN), 512, SM1>>>(
        xh, w1h, w1l, ybuf, s1, s2, (size_t)LL * CI1, (size_t)5 * 1 * CO * 64, LL);
    inorm_finalize<<<(NN * CO + 255) / 256, 256>>>(s1, s2, l1_gamma, l1_beta, scl, shf);
    norm_transpose_kernel<<<dim3(LL / 32, NN), 256>>>(ybuf, scl, shf, nullptr, hh);

    // layer 2
    gate_weights_kernel<<<dim3(NN, CO / 64, 4), 512>>>(t, l2_gw, l2_gb, l2_k5, l2_k3, l2_k1,
                                                       l2_a3, l2_a5, w2h, w2l, s1, s2, CO);
    mma_conv<128, 5, 1, 4, 256, true><<<dim3(LL / 256, NN), 512, SM2>>>(
        hh, w2h, w2l, ybuf, s1, s2, (size_t)LL * CO, (size_t)5 * 2 * CO * 64, LL);
    inorm_finalize<<<(NN * CO + 255) / 256, 256>>>(s1, s2, l2_gamma, l2_beta, scl, shf);
    norm_transpose_kernel<<<dim3(LL / 32, NN), 256>>>(ybuf, scl, shf, out_skip, ssh);

    // downsample + BN + mish
    split_dw_kernel<<<(CO * 256 + 255) / 256, 256>>>(dw, wdh, wdl, b1, b2);
    mma_conv<128, 2, 2, 0, 128, false><<<dim3(LO / 128, NN), 512, SMD>>>(
        ssh, wdh, wdl, xdbuf, b1, b2, (size_t)LL * CO, 0, LO);
    bn_finalize<<<1, 128>>>(b1, b2, dg, db, bsc, bsh);
    bn_apply_kernel<<<(int)(((size_t)NN * CO * LO / 4 + 255) / 256), 256>>>(xdbuf, bsc, bsh, out_xd);
}

// round 9
// speedup vs baseline: 1.3943x; 1.0516x over previous
#include <cuda_runtime.h>
#include <cuda_fp16.h>
#include <math.h>
#include <stdint.h>

#define NN 32
#define LL 8192
#define CO 128
#define CI1 64
#define TT 10
#define LO 4096

// ---------------- scratch (__device__ globals; no allocation) ----------------
__device__ __align__(128) __half g_xh[(size_t)NN * LL * CI1];
__device__ __align__(128) __half g_hh[(size_t)NN * LL * CO];
__device__ __align__(128) __half g_ssh[(size_t)NN * LL * CO];
__device__ __align__(128) float g_y[(size_t)NN * CO * LL];
__device__ __align__(128) __half g_w1h[(size_t)NN * 5 * 1 * CO * 64];
__device__ __align__(128) __half g_w1l[(size_t)NN * 5 * 1 * CO * 64];
__device__ __align__(128) __half g_w2h[(size_t)NN * 5 * 2 * CO * 64];
__device__ __align__(128) __half g_w2l[(size_t)NN * 5 * 2 * CO * 64];
__device__ __align__(128) __half g_wdh[4 * CO * 64];
__device__ __align__(128) __half g_wdl[4 * CO * 64];
__device__ __align__(128) float g_xd[(size_t)NN * CO * LO];
__device__ float g_s1[NN * CO];
__device__ float g_s2[NN * CO];
__device__ float g_b1[CO];
__device__ float g_b2[CO];
__device__ float g_scale[NN * CO];
__device__ float g_shift[NN * CO];
__device__ float g_bscale[CO];
__device__ float g_bshift[CO];

// ---------------- small device helpers ----------------
__device__ __forceinline__ float mishf(float v) {
    float sp = (v > 20.f) ? v : log1pf(expf(v));
    return v * tanhf(sp);
}
__device__ __forceinline__ uint32_t smem_u32(const void* p) {
    uint32_t a;
    asm("{ .reg .u64 t; cvta.to.shared.u64 t, %1; cvt.u32.u64 %0, t; }" : "=r"(a) : "l"(p));
    return a;
}
__device__ __forceinline__ void cp16(uint32_t dst, const void* src) {
    asm volatile("cp.async.cg.shared.global [%0], [%1], 16;" :: "r"(dst), "l"(src));
}
__device__ __forceinline__ void cp_commit() {
    asm volatile("cp.async.commit_group;" ::: "memory");
}
template <int N>
__device__ __forceinline__ void cp_wait() {
    asm volatile("cp.async.wait_group %0;" :: "n"(N) : "memory");
}
__device__ __forceinline__ void ldsm4(uint32_t* r, uint32_t addr) {
    asm volatile("ldmatrix.sync.aligned.m8n8.x4.shared.b16 {%0,%1,%2,%3}, [%4];"
                 : "=r"(r[0]), "=r"(r[1]), "=r"(r[2]), "=r"(r[3]) : "r"(addr));
}
__device__ __forceinline__ void mma_f16(float* d, const uint32_t* a, const uint32_t* b) {
    asm volatile("mma.sync.aligned.m16n8k16.row.col.f32.f16.f16.f32 "
                 "{%0,%1,%2,%3}, {%4,%5,%6,%7}, {%8,%9}, {%0,%1,%2,%3};"
                 : "+f"(d[0]), "+f"(d[1]), "+f"(d[2]), "+f"(d[3])
                 : "r"(a[0]), "r"(a[1]), "r"(a[2]), "r"(a[3]), "r"(b[0]), "r"(b[1]));
}
__device__ __forceinline__ void h_split(float v, __half& h, __half& l) {
    h = __float2half_rn(v);
    l = __float2half_rn(v - __half2float(h));
}

// ============================================================================
// Conv-as-GEMM, warp-level fp16 MMA, 2-term W-split.
// NEW SHAPE: CTA = 256 threads (8 warps, 2x4), tile M=64 (o-half via
// blockIdx.z) x NT=128 (l). Small smem + <=85 regs => 2-3 CTAs/SM so
// piece-boundary waits are hidden by co-resident CTAs.
//   Y[n, o, l0+j] = sum_{k<NSHIFT, i<CI} W[n,o,i,k] * X[n, RS*(l0+j)+k-HALO, i]
// ============================================================================
template <int CI, int NSHIFT, int RS, int HALO, int NT, bool PER_N_STATS>
__global__ void __launch_bounds__(256, 3)
mma_conv(const __half* __restrict__ X,
         const __half* __restrict__ Wh, const __half* __restrict__ Wl,
         float* __restrict__ Y, float* __restrict__ S1, float* __restrict__ S2,
         size_t x_nstride, size_t w_nstride, int outL)
{
    constexpr int HF = CI / 64;
    constexpr int P = NSHIFT * HF;
    constexpr int XR = NT * RS + HALO;
    constexpr int XPITCH = CI * 2 + 16;      // bytes; row step ≡ 4 banks (mod 32)
    constexpr int WPITCH = 144;
    constexpr int WCH = 64 * WPITCH;         // 64-row W chunk (this CTA's o-half)
    constexpr int XT = XR * XPITCH;
    constexpr int SEGR = CI / 8;
    constexpr int NB = NT / 64;              // 16-col B blocks per warp (nspan 32)
    constexpr int NFR = 2 * NB;

    extern __shared__ char sm[];
    const uint32_t base = smem_u32(sm);
    const uint32_t x_s = base;
    const uint32_t w_s = base + XT;

    const int tid = threadIdx.x;
    const int n = blockIdx.y;
    const int l0 = blockIdx.x * NT;
    const int o_base = blockIdx.z * 64;

    if (HALO > 0 && blockIdx.x == 0) {
        const uint4 z = make_uint4(0, 0, 0, 0);
        for (int s = tid; s < HALO * SEGR; s += 256) {
            int r = s / SEGR, c = s % SEGR;
            *(uint4*)(sm + r * XPITCH + c * 16) = z;
        }
    }
    {   // X tile
        const __half* gx = X + (size_t)n * x_nstride;
        for (int s = tid; s < XR * SEGR; s += 256) {
            int r = s / SEGR, c = s % SEGR;
            long l = (long)l0 * RS - HALO + r;
            if (l >= 0)
                cp16(x_s + r * XPITCH + c * 16, gx + (size_t)l * CI + (size_t)c * 8);
        }
    }
    // W loader: 64 rows (this o-half), hi | lo, one commit group per piece
    auto load_w = [&](int piece, int buf) {
        const __half* ph = Wh + (size_t)n * w_nstride + (size_t)piece * (CO * 64)
                           + (size_t)o_base * 64;
        const __half* pl = Wl + (size_t)n * w_nstride + (size_t)piece * (CO * 64)
                           + (size_t)o_base * 64;
        uint32_t dst = w_s + (uint32_t)buf * (2 * WCH);
        for (int s = tid; s < 512; s += 256) {
            int r = s >> 3, c = s & 7;
            cp16(dst + r * WPITCH + c * 16, ph + r * 64 + c * 8);
            cp16(dst + WCH + r * WPITCH + c * 16, pl + r * 64 + c * 8);
        }
        cp_commit();
    };
    load_w(0, 0);

    const int warp = tid >> 5, lane = tid & 31;
    const int o0w = (warp >> 2) * 32;        // warp row (0 or 32)
    const int n0w = (warp & 3) * (NT / 4);   // warp col (32 span)
    const int a_row = (lane & 7) + ((lane >> 3) & 1) * 8;
    const int a_csh = (lane >> 4) * 8;
    const int b_jj = (lane & 7) + ((lane >> 4) << 3);
    const int b_csh = ((lane >> 3) & 1) * 8;

    float acc[2][NFR][4];
#pragma unroll
    for (int mi = 0; mi < 2; mi++)
#pragma unroll
        for (int nf = 0; nf < NFR; nf++)
#pragma unroll
            for (int q = 0; q < 4; q++) acc[mi][nf][q] = 0.f;

    for (int p = 0; p < P; p++) {
        cp_wait<0>();
        __syncthreads();   // readers of buffer (p+1)&1 (= piece p-1) are done
        if (p + 1 < P) load_w(p + 1, (p + 1) & 1);

        const int k = p / HF, hf = p % HF;
        const uint32_t wh_b = w_s + (uint32_t)(p & 1) * (2 * WCH);
        const uint32_t wl_b = wh_b + WCH;

#pragma unroll
        for (int i16 = 0; i16 < 4; i16++) {
            const int i0 = i16 * 16;
            uint32_t Ah[2][4], Al[2][4];
#pragma unroll
            for (int mi = 0; mi < 2; mi++) {
                uint32_t ao = (uint32_t)((o0w + a_row + mi * 16) * WPITCH + (i0 + a_csh) * 2);
                ldsm4(Ah[mi], wh_b + ao);
                ldsm4(Al[mi], wl_b + ao);
            }
            const int xcol = (hf * 64 + i0 + b_csh) * 2;
#pragma unroll
            for (int nb = 0; nb < NB; nb++) {
                uint32_t B[4];
                uint32_t xo = (uint32_t)((RS * (n0w + nb * 16 + b_jj) + k) * XPITCH + xcol);
                ldsm4(B, x_s + xo);
#pragma unroll
                for (int mi = 0; mi < 2; mi++)
#pragma unroll
                    for (int hl = 0; hl < 2; hl++) {
                        float* d = acc[mi][nb * 2 + hl];
                        mma_f16(d, Ah[mi], &B[hl * 2]);
                        mma_f16(d, Al[mi], &B[hl * 2]);
                    }
            }
        }
    }

    // ---------------- epilogue: store + fused stats ----------------
    const int g = lane >> 2, tg = lane & 3;
#pragma unroll
    for (int mi = 0; mi < 2; mi++) {
        const int o = o_base + o0w + mi * 16 + g;
        float* row0 = Y + ((size_t)(n * CO + o)) * outL + l0 + n0w;
        float* row1 = row0 + (size_t)8 * outL;
#pragma unroll
        for (int nf = 0; nf < NFR; nf++) {
            int c = nf * 8 + tg * 2;
            *(float2*)(row0 + c) = make_float2(acc[mi][nf][0], acc[mi][nf][1]);
            *(float2*)(row1 + c) = make_float2(acc[mi][nf][2], acc[mi][nf][3]);
        }
    }
    float ts[4], tq[4];
#pragma unroll
    for (int r = 0; r < 4; r++) { ts[r] = 0.f; tq[r] = 0.f; }
#pragma unroll
    for (int mi = 0; mi < 2; mi++)
#pragma unroll
        for (int nf = 0; nf < NFR; nf++) {
            float a0 = acc[mi][nf][0], a1 = acc[mi][nf][1];
            float a2 = acc[mi][nf][2], a3 = acc[mi][nf][3];
            ts[2 * mi]     += a0 + a1;  tq[2 * mi]     += a0 * a0 + a1 * a1;
            ts[2 * mi + 1] += a2 + a3;  tq[2 * mi + 1] += a2 * a2 + a3 * a3;
        }
#pragma unroll
    for (int r = 0; r < 4; r++) {
        ts[r] += __shfl_xor_sync(0xffffffffu, ts[r], 1);
        ts[r] += __shfl_xor_sync(0xffffffffu, ts[r], 2);
        tq[r] += __shfl_xor_sync(0xffffffffu, tq[r], 1);
        tq[r] += __shfl_xor_sync(0xffffffffu, tq[r], 2);
    }
    if (tg == 0) {
        const int sbase = PER_N_STATS ? n * CO : 0;
#pragma unroll
        for (int r = 0; r < 4; r++) {
            int o = o_base + o0w + (r >> 1) * 16 + g + (r & 1) * 8;
            atomicAdd(&S1[sbase + o], ts[r]);
            atomicAdd(&S2[sbase + o], tq[r]);
        }
    }
}

// ---------------- fp32 -> fp16 ----------------
__global__ void split_x_kernel(const float* __restrict__ src,
                               __half* __restrict__ hi, size_t count4)
{
    size_t i = (size_t)blockIdx.x * 256 + threadIdx.x;
    if (i >= count4) return;
    float4 v = ((const float4*)src)[i];
    ((__half2*)hi)[2 * i]     = __floats2half2_rn(v.x, v.y);
    ((__half2*)hi)[2 * i + 1] = __floats2half2_rn(v.z, v.w);
}

// ---------------- gate + per-sample weights (fp16 hi/lo) ----------------
// grid (NN, HF, 4), block 512 = 8 o-lanes x 64 ii-lanes. Gates in smem,
// coalesced W writes (ii contiguous), near-contiguous expert reads.
__global__ void __launch_bounds__(512)
gate_weights_kernel(const float* __restrict__ t,
                    const float* __restrict__ gw,
                    const float* __restrict__ gb,
                    const float* __restrict__ k5,
                    const float* __restrict__ k3,
                    const float* __restrict__ k1,
                    const float* __restrict__ a3,
                    const float* __restrict__ a5,
                    __half* __restrict__ wh,
                    __half* __restrict__ wl,
                    float* __restrict__ S1, float* __restrict__ S2,
                    int CI)
{
    const int n = blockIdx.x;
    const int hf = blockIdx.y;
    const int HF = gridDim.y;
    const int oc = blockIdx.z;           // o chunk: [oc*32, oc*32+32)
    const int tid = threadIdx.x;

    __shared__ float gs[5][128];
    if (tid < 128) {
        const int o = tid;
        if (blockIdx.y == 0 && blockIdx.z == 0) {
            S1[n * CO + o] = 0.f;
            S2[n * CO + o] = 0.f;
        }
        float tv[TT];
#pragma unroll
        for (int j = 0; j < TT; j++) tv[j] = t[n * TT + j];
        float g[5];
        float mx = -1e30f;
#pragma unroll
        for (int e = 0; e < 5; e++) {
            float s = gb[e * CO + o];
            const float* gwr = gw + (size_t)(e * CO + o) * TT;
#pragma unroll
            for (int j = 0; j < TT; j++) s += tv[j] * gwr[j];
            g[e] = s;
            mx = fmaxf(mx, s);
        }
        float den = 0.f;
#pragma unroll
        for (int e = 0; e < 5; e++) { g[e] = expf(g[e] - mx); den += g[e]; }
        float inv = 1.f / den;
        gs[0][o] = g[0] * inv;
        gs[1][o] = g[1] * inv;
        gs[2][o] = g[2] * inv;
        gs[3][o] = g[3] * inv * (1.f / 3.f);
        gs[4][o] = g[4] * inv * 0.2f;
    }
    __syncthreads();

    const int og = tid >> 6;             // 0..7
    const int ii = tid & 63;
    const int i = hf * 64 + ii;
    const size_t kstride = (size_t)HF * 128 * 64;

#pragma unroll
    for (int oj = 0; oj < 4; oj++) {
        const int o = oc * 32 + oj * 8 + og;
        const float g0 = gs[0][o], g1 = gs[1][o], g2 = gs[2][o];
        const float g3v = gs[3][o], g4v = gs[4][o];
        const int oi = o * CI + i;
        const float* p5 = k5 + (size_t)oi * 5;
        const float* p3 = k3 + (size_t)oi * 3;
        const float bse = g4v * a5[oi];
        const float c3v = g3v * a3[oi];
        float wv[5];
        wv[0] = g0 * p5[0] + bse;
        wv[1] = g0 * p5[1] + bse;
        wv[2] = g0 * p5[2] + g1 * p3[0] + c3v + bse;
        wv[3] = g0 * p5[3] + g1 * p3[1] + c3v + bse;
        wv[4] = g0 * p5[4] + g1 * p3[2] + c3v + g2 * k1[oi] + bse;
        const size_t idx0 = (((size_t)n * 5 * HF + hf) * 128 + o) * 64 + ii;
#pragma unroll
        for (int k = 0; k < 5; k++) {
            __half h, l;
            h_split(wv[k], h, l);
            wh[idx0 + k * kstride] = h;
            wl[idx0 + k * kstride] = l;
        }
    }
}

// ---------------- downsample weight reorder + split (+ zero bn accums) -------
__global__ void split_dw_kernel(const float* __restrict__ dw,
                                __half* __restrict__ wdh,
                                __half* __restrict__ wdl,
                                float* __restrict__ B1, float* __restrict__ B2)
{
    int idx = blockIdx.x * 256 + threadIdx.x;
    if (blockIdx.x == 0) {
        if (threadIdx.x < CO) B1[threadIdx.x] = 0.f;
        else B2[threadIdx.x - CO] = 0.f;
    }
    if (idx >= CO * 256) return;
    int o = idx >> 8, r = idx & 255;
    int kk = r >> 7, ifull = r & 127;
    float v = dw[(size_t)o * 256 + ifull * 2 + kk];
    __half h, l;
    h_split(v, h, l);
    size_t out = (((size_t)kk * 2 + (ifull >> 6)) * 128 + o) * 64 + (ifull & 63);
    wdh[out] = h;
    wdl[out] = l;
}

// ---------------- finalize kernels ----------------
__global__ void inorm_finalize(const float* __restrict__ S1, const float* __restrict__ S2,
                               const float* __restrict__ gamma, const float* __restrict__ beta,
                               float* __restrict__ scale, float* __restrict__ shift)
{
    int no = blockIdx.x * 256 + threadIdx.x;
    if (no >= NN * CO) return;
    int o = no & (CO - 1);
    float mu = S1[no] * (1.f / LL);
    float var = S2[no] * (1.f / LL) - mu * mu;
    float sc = gamma[o] * rsqrtf(var + 1e-5f);
    scale[no] = sc;
    shift[no] = beta[o] - mu * sc;
}

__global__ void bn_finalize(const float* __restrict__ B1, const float* __restrict__ B2,
                            const float* __restrict__ dg, const float* __restrict__ db,
                            float* __restrict__ bs, float* __restrict__ bb)
{
    int o = threadIdx.x;
    if (o >= CO) return;
    const float cnt = (float)NN * LO;
    float mu = B1[o] / cnt;
    float var = B2[o] / cnt - mu * mu;
    float sc = dg[o] * rsqrtf(var + 1e-5f);
    bs[o] = sc;
    bb[o] = db[o] - mu * sc;
}

// ---------------- norm + mish + transpose (fp16 out, optional fp32 out) ------
__global__ void norm_transpose_kernel(const float* __restrict__ y,
                                      const float* __restrict__ scale,
                                      const float* __restrict__ shift,
                                      float* __restrict__ out_full,
                                      __half* __restrict__ out_hi)
{
    __shared__ float tile[CO][33];
    __shared__ float sc[CO], sh[CO];
    int n = blockIdx.y, l0 = blockIdx.x * 32;
    int tid = threadIdx.x;
    if (tid < CO) { sc[tid] = scale[n * CO + tid]; sh[tid] = shift[n * CO + tid]; }
    __syncthreads();
    int lt = tid & 31, ob = tid >> 5;
#pragma unroll
    for (int r = 0; r < 16; r++) {
        int o = ob + 8 * r;
        float v = y[((size_t)(n * CO + o)) * LL + l0 + lt];
        tile[o][lt] = mishf(v * sc[o] + sh[o]);
    }
    __syncthreads();
    int oc = tid & 127, lb = tid >> 7;
#pragma unroll
    for (int ly = lb; ly < 32; ly += 2) {
        size_t idx = ((size_t)n * LL + l0 + ly) * CO + oc;
        float v = tile[oc][ly];
        if (out_full) out_full[idx] = v;
        out_hi[idx] = __float2half_rn(v);
    }
}

// ---------------- batch-norm apply ----------------
__global__ void bn_apply_kernel(const float* __restrict__ xd,
                                const float* __restrict__ bs,
                                const float* __restrict__ bb,
                                float* __restrict__ out)
{
    size_t i4 = (size_t)blockIdx.x * 256 + threadIdx.x;
    const size_t total4 = (size_t)NN * CO * LO / 4;
    if (i4 >= total4) return;
    float4 v = ((const float4*)xd)[i4];
    int o = (int)((i4 * 4 / LO) & (CO - 1));
    float sc = bs[o], sh = bb[o];
    float4 r;
    r.x = mishf(v.x * sc + sh);
    r.y = mishf(v.y * sc + sh);
    r.z = mishf(v.z * sc + sh);
    r.w = mishf(v.w * sc + sh);
    ((float4*)out)[i4] = r;
}

// ---------------- launch ----------------
extern "C" void kernel_launch(void* const* d_in, const int* in_sizes, int n_in,
                              void* d_out, int out_size)
{
    const float* x        = (const float*)d_in[0];
    const float* t        = (const float*)d_in[1];
    const float* l1_k5    = (const float*)d_in[2];
    const float* l1_k3    = (const float*)d_in[3];
    const float* l1_k1    = (const float*)d_in[4];
    const float* l1_a3    = (const float*)d_in[5];
    const float* l1_a5    = (const float*)d_in[6];
    const float* l1_gw    = (const float*)d_in[7];
    const float* l1_gb    = (const float*)d_in[8];
    const float* l1_gamma = (const float*)d_in[9];
    const float* l1_beta  = (const float*)d_in[10];
    const float* l2_k5    = (const float*)d_in[11];
    const float* l2_k3    = (const float*)d_in[12];
    const float* l2_k1    = (const float*)d_in[13];
    const float* l2_a3    = (const float*)d_in[14];
    const float* l2_a5    = (const float*)d_in[15];
    const float* l2_gw    = (const float*)d_in[16];
    const float* l2_gb    = (const float*)d_in[17];
    const float* l2_gamma = (const float*)d_in[18];
    const float* l2_beta  = (const float*)d_in[19];
    const float* dw       = (const float*)d_in[20];
    const float* dg       = (const float*)d_in[21];
    const float* db       = (const float*)d_in[22];

    float* out      = (float*)d_out;
    float* out_xd   = out;
    float* out_skip = out + (size_t)NN * CO * LO;

    __half *xh, *hh, *ssh, *w1h, *w1l, *w2h, *w2l, *wdh, *wdl;
    float *ybuf, *xdbuf, *scl, *shf, *bsc, *bsh, *s1, *s2, *b1, *b2;
    cudaGetSymbolAddress((void**)&xh, g_xh);
    cudaGetSymbolAddress((void**)&hh, g_hh);
    cudaGetSymbolAddress((void**)&ssh, g_ssh);
    cudaGetSymbolAddress((void**)&ybuf, g_y);
    cudaGetSymbolAddress((void**)&w1h, g_w1h);
    cudaGetSymbolAddress((void**)&w1l, g_w1l);
    cudaGetSymbolAddress((void**)&w2h, g_w2h);
    cudaGetSymbolAddress((void**)&w2l, g_w2l);
    cudaGetSymbolAddress((void**)&wdh, g_wdh);
    cudaGetSymbolAddress((void**)&wdl, g_wdl);
    cudaGetSymbolAddress((void**)&xdbuf, g_xd);
    cudaGetSymbolAddress((void**)&scl, g_scale);
    cudaGetSymbolAddress((void**)&shf, g_shift);
    cudaGetSymbolAddress((void**)&bsc, g_bscale);
    cudaGetSymbolAddress((void**)&bsh, g_bshift);
    cudaGetSymbolAddress((void**)&s1, g_s1);
    cudaGetSymbolAddress((void**)&s2, g_s2);
    cudaGetSymbolAddress((void**)&b1, g_b1);
    cudaGetSymbolAddress((void**)&b2, g_b2);

    // smem: XT + 2 buffers * (hi+lo) * 64*144
    const int SM1 = 132 * 144 + 4 * 9216;   // 55872
    const int SM2 = 132 * 272 + 4 * 9216;   // 72768
    const int SMD = 256 * 272 + 4 * 9216;   // 106496
    cudaFuncSetAttribute((const void*)mma_conv<64, 5, 1, 4, 128, true>,
                         cudaFuncAttributeMaxDynamicSharedMemorySize, SM1);
    cudaFuncSetAttribute((const void*)mma_conv<128, 5, 1, 4, 128, true>,
                         cudaFuncAttributeMaxDynamicSharedMemorySize, SM2);
    cudaFuncSetAttribute((const void*)mma_conv<128, 2, 2, 0, 128, false>,
                         cudaFuncAttributeMaxDynamicSharedMemorySize, SMD);

    // x -> fp16
    {
        size_t c4 = (size_t)NN * LL * CI1 / 4;
        split_x_kernel<<<(int)((c4 + 255) / 256), 256>>>(x, xh, c4);
    }

    // layer 1
    gate_weights_kernel<<<dim3(NN, CI1 / 64, 4), 512>>>(t, l1_gw, l1_gb, l1_k5, l1_k3, l1_k1,
                                                        l1_a3, l1_a5, w1h, w1l, s1, s2, CI1);
    mma_conv<64, 5, 1, 4, 128, true><<<dim3(LL / 128, NN, 2), 256, SM1>>>(
        xh, w1h, w1l, ybuf, s1, s2, (size_t)LL * CI1, (size_t)5 * 1 * CO * 64, LL);
    inorm_finalize<<<(NN * CO + 255) / 256, 256>>>(s1, s2, l1_gamma, l1_beta, scl, shf);
    norm_transpose_kernel<<<dim3(LL / 32, NN), 256>>>(ybuf, scl, shf, nullptr, hh);

    // layer 2
    gate_weights_kernel<<<dim3(NN, CO / 64, 4), 512>>>(t, l2_gw, l2_gb, l2_k5, l2_k3, l2_k1,
                                                       l2_a3, l2_a5, w2h, w2l, s1, s2, CO);
    mma_conv<128, 5, 1, 4, 128, true><<<dim3(LL / 128, NN, 2), 256, SM2>>>(
        hh, w2h, w2l, ybuf, s1, s2, (size_t)LL * CO, (size_t)5 * 2 * CO * 64, LL);
    inorm_finalize<<<(NN * CO + 255) / 256, 256>>>(s1, s2, l2_gamma, l2_beta, scl, shf);
    norm_transpose_kernel<<<dim3(LL / 32, NN), 256>>>(ybuf, scl, shf, out_skip, ssh);

    // downsample + BN + mish
    split_dw_kernel<<<(CO * 256 + 255) / 256, 256>>>(dw, wdh, wdl, b1, b2);
    mma_conv<128, 2, 2, 0, 128, false><<<dim3(LO / 128, NN, 2), 256, SMD>>>(
        ssh, wdh, wdl, xdbuf, b1, b2, (size_t)LL * CO, 0, LO);
    bn_finalize<<<1, 128>>>(b1, b2, dg, db, bsc, bsh);
    bn_apply_kernel<<<(int)(((size_t)NN * CO * LO / 4 + 255) / 256), 256>>>(xdbuf, bsc, bsh, out_xd);
}

// round 10
// speedup vs baseline: 1.6232x; 1.1641x over previous
#include <cuda_runtime.h>
#include <cuda_fp16.h>
#include <math.h>
#include <stdint.h>

#define NN 32
#define LL 8192
#define CO 128
#define CI1 64
#define TT 10
#define LO 4096

// ---------------- scratch (__device__ globals; no allocation) ----------------
__device__ __align__(128) __half g_xh[(size_t)NN * LL * CI1];
__device__ __align__(128) __half g_hh[(size_t)NN * LL * CO];
__device__ __align__(128) __half g_ssh[(size_t)NN * LL * CO];
__device__ __align__(128) float g_y[(size_t)NN * CO * LL];
__device__ __align__(128) __half g_w1h[(size_t)NN * 5 * 1 * CO * 64];
__device__ __align__(128) __half g_w1l[(size_t)NN * 5 * 1 * CO * 64];
__device__ __align__(128) __half g_w2h[(size_t)NN * 5 * 2 * CO * 64];
__device__ __align__(128) __half g_w2l[(size_t)NN * 5 * 2 * CO * 64];
__device__ __align__(128) __half g_wdh[4 * CO * 64];
__device__ __align__(128) __half g_wdl[4 * CO * 64];
__device__ __align__(128) float g_xd[(size_t)NN * CO * LO];
__device__ float g_s1[NN * CO];
__device__ float g_s2[NN * CO];
__device__ float g_b1[CO];
__device__ float g_b2[CO];
__device__ float g_scale[NN * CO];
__device__ float g_shift[NN * CO];
__device__ float g_bscale[CO];
__device__ float g_bshift[CO];

// ---------------- small device helpers ----------------
__device__ __forceinline__ float mishf(float v) {
    float sp = (v > 20.f) ? v : log1pf(expf(v));
    return v * tanhf(sp);
}
__device__ __forceinline__ uint32_t smem_u32(const void* p) {
    uint32_t a;
    asm("{ .reg .u64 t; cvta.to.shared.u64 t, %1; cvt.u32.u64 %0, t; }" : "=r"(a) : "l"(p));
    return a;
}
__device__ __forceinline__ void cp16(uint32_t dst, const void* src) {
    asm volatile("cp.async.cg.shared.global [%0], [%1], 16;" :: "r"(dst), "l"(src));
}
__device__ __forceinline__ void cp_commit() {
    asm volatile("cp.async.commit_group;" ::: "memory");
}
template <int N>
__device__ __forceinline__ void cp_wait() {
    asm volatile("cp.async.wait_group %0;" :: "n"(N) : "memory");
}
__device__ __forceinline__ void ldsm4(uint32_t* r, uint32_t addr) {
    asm volatile("ldmatrix.sync.aligned.m8n8.x4.shared.b16 {%0,%1,%2,%3}, [%4];"
                 : "=r"(r[0]), "=r"(r[1]), "=r"(r[2]), "=r"(r[3]) : "r"(addr));
}
__device__ __forceinline__ void mma_f16(float* d, const uint32_t* a, const uint32_t* b) {
    asm volatile("mma.sync.aligned.m16n8k16.row.col.f32.f16.f16.f32 "
                 "{%0,%1,%2,%3}, {%4,%5,%6,%7}, {%8,%9}, {%0,%1,%2,%3};"
                 : "+f"(d[0]), "+f"(d[1]), "+f"(d[2]), "+f"(d[3])
                 : "r"(a[0]), "r"(a[1]), "r"(a[2]), "r"(a[3]), "r"(b[0]), "r"(b[1]));
}
__device__ __forceinline__ void h_split(float v, __half& h, __half& l) {
    h = __float2half_rn(v);
    l = __float2half_rn(v - __half2float(h));
}

// ============================================================================
// Conv-as-GEMM, warp-level fp16 MMA.
// TWO_TERM=1: W = hi+lo fp16 (2 MMAs per fragment). TWO_TERM=0: W = hi only.
// CTA = 256 threads (8 warps, 2x4), tile M=64 (o-half via blockIdx.z) x NT.
//   Y[n, o, l0+j] = sum_{k<NSHIFT, i<CI} W[n,o,i,k] * X[n, RS*(l0+j)+k-HALO, i]
// ============================================================================
template <int CI, int NSHIFT, int RS, int HALO, int NT, bool PER_N_STATS, bool TWO_TERM>
__global__ void __launch_bounds__(256, 3)
mma_conv(const __half* __restrict__ X,
         const __half* __restrict__ Wh, const __half* __restrict__ Wl,
         float* __restrict__ Y, float* __restrict__ S1, float* __restrict__ S2,
         size_t x_nstride, size_t w_nstride, int outL)
{
    constexpr int HF = CI / 64;
    constexpr int P = NSHIFT * HF;
    constexpr int XR = NT * RS + HALO;
    constexpr int XPITCH = CI * 2 + 16;      // bytes; row step ≡ 4 banks (mod 32)
    constexpr int WPITCH = 144;
    constexpr int WCH = 64 * WPITCH;         // 64-row W chunk (this CTA's o-half)
    constexpr int WBUF = (TWO_TERM ? 2 : 1) * WCH;
    constexpr int XT = XR * XPITCH;
    constexpr int SEGR = CI / 8;
    constexpr int NB = NT / 64;              // 16-col B blocks per warp (nspan 32)
    constexpr int NFR = 2 * NB;

    extern __shared__ char sm[];
    const uint32_t base = smem_u32(sm);
    const uint32_t x_s = base;
    const uint32_t w_s = base + XT;

    const int tid = threadIdx.x;
    const int n = blockIdx.y;
    const int l0 = blockIdx.x * NT;
    const int o_base = blockIdx.z * 64;

    if (HALO > 0 && blockIdx.x == 0) {
        const uint4 z = make_uint4(0, 0, 0, 0);
        for (int s = tid; s < HALO * SEGR; s += 256) {
            int r = s / SEGR, c = s % SEGR;
            *(uint4*)(sm + r * XPITCH + c * 16) = z;
        }
    }
    {   // X tile
        const __half* gx = X + (size_t)n * x_nstride;
        for (int s = tid; s < XR * SEGR; s += 256) {
            int r = s / SEGR, c = s % SEGR;
            long l = (long)l0 * RS - HALO + r;
            if (l >= 0)
                cp16(x_s + r * XPITCH + c * 16, gx + (size_t)l * CI + (size_t)c * 8);
        }
    }
    // W loader: 64 rows (this o-half), hi (and lo if TWO_TERM)
    auto load_w = [&](int piece, int buf) {
        const __half* ph = Wh + (size_t)n * w_nstride + (size_t)piece * (CO * 64)
                           + (size_t)o_base * 64;
        uint32_t dst = w_s + (uint32_t)buf * WBUF;
        for (int s = tid; s < 512; s += 256) {
            int r = s >> 3, c = s & 7;
            cp16(dst + r * WPITCH + c * 16, ph + r * 64 + c * 8);
        }
        if (TWO_TERM) {
            const __half* pl = Wl + (size_t)n * w_nstride + (size_t)piece * (CO * 64)
                               + (size_t)o_base * 64;
            for (int s = tid; s < 512; s += 256) {
                int r = s >> 3, c = s & 7;
                cp16(dst + WCH + r * WPITCH + c * 16, pl + r * 64 + c * 8);
            }
        }
        cp_commit();
    };
    load_w(0, 0);

    const int warp = tid >> 5, lane = tid & 31;
    const int o0w = (warp >> 2) * 32;        // warp row (0 or 32)
    const int n0w = (warp & 3) * (NT / 4);   // warp col (32 span)
    const int a_row = (lane & 7) + ((lane >> 3) & 1) * 8;
    const int a_csh = (lane >> 4) * 8;
    const int b_jj = (lane & 7) + ((lane >> 4) << 3);
    const int b_csh = ((lane >> 3) & 1) * 8;

    float acc[2][NFR][4];
#pragma unroll
    for (int mi = 0; mi < 2; mi++)
#pragma unroll
        for (int nf = 0; nf < NFR; nf++)
#pragma unroll
            for (int q = 0; q < 4; q++) acc[mi][nf][q] = 0.f;

    for (int p = 0; p < P; p++) {
        cp_wait<0>();
        __syncthreads();   // readers of buffer (p+1)&1 (= piece p-1) are done
        if (p + 1 < P) load_w(p + 1, (p + 1) & 1);

        const int k = p / HF, hf = p % HF;
        const uint32_t wh_b = w_s + (uint32_t)(p & 1) * WBUF;
        const uint32_t wl_b = wh_b + WCH;

#pragma unroll
        for (int i16 = 0; i16 < 4; i16++) {
            const int i0 = i16 * 16;
            uint32_t Ah[2][4], Al[2][4];
#pragma unroll
            for (int mi = 0; mi < 2; mi++) {
                uint32_t ao = (uint32_t)((o0w + a_row + mi * 16) * WPITCH + (i0 + a_csh) * 2);
                ldsm4(Ah[mi], wh_b + ao);
                if (TWO_TERM) ldsm4(Al[mi], wl_b + ao);
            }
            const int xcol = (hf * 64 + i0 + b_csh) * 2;
#pragma unroll
            for (int nb = 0; nb < NB; nb++) {
                uint32_t B[4];
                uint32_t xo = (uint32_t)((RS * (n0w + nb * 16 + b_jj) + k) * XPITCH + xcol);
                ldsm4(B, x_s + xo);
#pragma unroll
                for (int mi = 0; mi < 2; mi++)
#pragma unroll
                    for (int hl = 0; hl < 2; hl++) {
                        float* d = acc[mi][nb * 2 + hl];
                        mma_f16(d, Ah[mi], &B[hl * 2]);
                        if (TWO_TERM) mma_f16(d, Al[mi], &B[hl * 2]);
                    }
            }
        }
    }

    // ---------------- epilogue: store + fused stats ----------------
    const int g = lane >> 2, tg = lane & 3;
#pragma unroll
    for (int mi = 0; mi < 2; mi++) {
        const int o = o_base + o0w + mi * 16 + g;
        float* row0 = Y + ((size_t)(n * CO + o)) * outL + l0 + n0w;
        float* row1 = row0 + (size_t)8 * outL;
#pragma unroll
        for (int nf = 0; nf < NFR; nf++) {
            int c = nf * 8 + tg * 2;
            *(float2*)(row0 + c) = make_float2(acc[mi][nf][0], acc[mi][nf][1]);
            *(float2*)(row1 + c) = make_float2(acc[mi][nf][2], acc[mi][nf][3]);
        }
    }
    float ts[4], tq[4];
#pragma unroll
    for (int r = 0; r < 4; r++) { ts[r] = 0.f; tq[r] = 0.f; }
#pragma unroll
    for (int mi = 0; mi < 2; mi++)
#pragma unroll
        for (int nf = 0; nf < NFR; nf++) {
            float a0 = acc[mi][nf][0], a1 = acc[mi][nf][1];
            float a2 = acc[mi][nf][2], a3 = acc[mi][nf][3];
            ts[2 * mi]     += a0 + a1;  tq[2 * mi]     += a0 * a0 + a1 * a1;
            ts[2 * mi + 1] += a2 + a3;  tq[2 * mi + 1] += a2 * a2 + a3 * a3;
        }
#pragma unroll
    for (int r = 0; r < 4; r++) {
        ts[r] += __shfl_xor_sync(0xffffffffu, ts[r], 1);
        ts[r] += __shfl_xor_sync(0xffffffffu, ts[r], 2);
        tq[r] += __shfl_xor_sync(0xffffffffu, tq[r], 1);
        tq[r] += __shfl_xor_sync(0xffffffffu, tq[r], 2);
    }
    if (tg == 0) {
        const int sbase = PER_N_STATS ? n * CO : 0;
#pragma unroll
        for (int r = 0; r < 4; r++) {
            int o = o_base + o0w + (r >> 1) * 16 + g + (r & 1) * 8;
            atomicAdd(&S1[sbase + o], ts[r]);
            atomicAdd(&S2[sbase + o], tq[r]);
        }
    }
}

// ---------------- fp32 -> fp16 ----------------
__global__ void split_x_kernel(const float* __restrict__ src,
                               __half* __restrict__ hi, size_t count4)
{
    size_t i = (size_t)blockIdx.x * 256 + threadIdx.x;
    if (i >= count4) return;
    float4 v = ((const float4*)src)[i];
    ((__half2*)hi)[2 * i]     = __floats2half2_rn(v.x, v.y);
    ((__half2*)hi)[2 * i + 1] = __floats2half2_rn(v.z, v.w);
}

// ---------------- gate + per-sample weights (fp16, optional lo plane) --------
// grid (NN, HF, 4), block 512 = 8 o-lanes x 64 ii-lanes.
__global__ void __launch_bounds__(512)
gate_weights_kernel(const float* __restrict__ t,
                    const float* __restrict__ gw,
                    const float* __restrict__ gb,
                    const float* __restrict__ k5,
                    const float* __restrict__ k3,
                    const float* __restrict__ k1,
                    const float* __restrict__ a3,
                    const float* __restrict__ a5,
                    __half* __restrict__ wh,
                    __half* __restrict__ wl,        // may be nullptr
                    float* __restrict__ S1, float* __restrict__ S2,
                    int CI)
{
    const int n = blockIdx.x;
    const int hf = blockIdx.y;
    const int HF = gridDim.y;
    const int oc = blockIdx.z;           // o chunk: [oc*32, oc*32+32)
    const int tid = threadIdx.x;

    __shared__ float gs[5][128];
    if (tid < 128) {
        const int o = tid;
        if (blockIdx.y == 0 && blockIdx.z == 0) {
            S1[n * CO + o] = 0.f;
            S2[n * CO + o] = 0.f;
        }
        float tv[TT];
#pragma unroll
        for (int j = 0; j < TT; j++) tv[j] = t[n * TT + j];
        float g[5];
        float mx = -1e30f;
#pragma unroll
        for (int e = 0; e < 5; e++) {
            float s = gb[e * CO + o];
            const float* gwr = gw + (size_t)(e * CO + o) * TT;
#pragma unroll
            for (int j = 0; j < TT; j++) s += tv[j] * gwr[j];
            g[e] = s;
            mx = fmaxf(mx, s);
        }
        float den = 0.f;
#pragma unroll
        for (int e = 0; e < 5; e++) { g[e] = expf(g[e] - mx); den += g[e]; }
        float inv = 1.f / den;
        gs[0][o] = g[0] * inv;
        gs[1][o] = g[1] * inv;
        gs[2][o] = g[2] * inv;
        gs[3][o] = g[3] * inv * (1.f / 3.f);
        gs[4][o] = g[4] * inv * 0.2f;
    }
    __syncthreads();

    const int og = tid >> 6;             // 0..7
    const int ii = tid & 63;
    const int i = hf * 64 + ii;
    const size_t kstride = (size_t)HF * 128 * 64;
    const bool write_lo = (wl != nullptr);

#pragma unroll
    for (int oj = 0; oj < 4; oj++) {
        const int o = oc * 32 + oj * 8 + og;
        const float g0 = gs[0][o], g1 = gs[1][o], g2 = gs[2][o];
        const float g3v = gs[3][o], g4v = gs[4][o];
        const int oi = o * CI + i;
        const float* p5 = k5 + (size_t)oi * 5;
        const float* p3 = k3 + (size_t)oi * 3;
        const float bse = g4v * a5[oi];
        const float c3v = g3v * a3[oi];
        float wv[5];
        wv[0] = g0 * p5[0] + bse;
        wv[1] = g0 * p5[1] + bse;
        wv[2] = g0 * p5[2] + g1 * p3[0] + c3v + bse;
        wv[3] = g0 * p5[3] + g1 * p3[1] + c3v + bse;
        wv[4] = g0 * p5[4] + g1 * p3[2] + c3v + g2 * k1[oi] + bse;
        const size_t idx0 = (((size_t)n * 5 * HF + hf) * 128 + o) * 64 + ii;
#pragma unroll
        for (int k = 0; k < 5; k++) {
            __half h = __float2half_rn(wv[k]);
            wh[idx0 + k * kstride] = h;
            if (write_lo)
                wl[idx0 + k * kstride] = __float2half_rn(wv[k] - __half2float(h));
        }
    }
}

// ---------------- downsample weight reorder + split (+ zero bn accums) -------
__global__ void split_dw_kernel(const float* __restrict__ dw,
                                __half* __restrict__ wdh,
                                __half* __restrict__ wdl,
                                float* __restrict__ B1, float* __restrict__ B2)
{
    int idx = blockIdx.x * 256 + threadIdx.x;
    if (blockIdx.x == 0) {
        if (threadIdx.x < CO) B1[threadIdx.x] = 0.f;
        else B2[threadIdx.x - CO] = 0.f;
    }
    if (idx >= CO * 256) return;
    int o = idx >> 8, r = idx & 255;
    int kk = r >> 7, ifull = r & 127;
    float v = dw[(size_t)o * 256 + ifull * 2 + kk];
    __half h, l;
    h_split(v, h, l);
    size_t out = (((size_t)kk * 2 + (ifull >> 6)) * 128 + o) * 64 + (ifull & 63);
    wdh[out] = h;
    wdl[out] = l;
}

// ---------------- finalize kernels ----------------
__global__ void inorm_finalize(const float* __restrict__ S1, const float* __restrict__ S2,
                               const float* __restrict__ gamma, const float* __restrict__ beta,
                               float* __restrict__ scale, float* __restrict__ shift)
{
    int no = blockIdx.x * 256 + threadIdx.x;
    if (no >= NN * CO) return;
    int o = no & (CO - 1);
    float mu = S1[no] * (1.f / LL);
    float var = S2[no] * (1.f / LL) - mu * mu;
    float sc = gamma[o] * rsqrtf(var + 1e-5f);
    scale[no] = sc;
    shift[no] = beta[o] - mu * sc;
}

__global__ void bn_finalize(const float* __restrict__ B1, const float* __restrict__ B2,
                            const float* __restrict__ dg, const float* __restrict__ db,
                            float* __restrict__ bs, float* __restrict__ bb)
{
    int o = threadIdx.x;
    if (o >= CO) return;
    const float cnt = (float)NN * LO;
    float mu = B1[o] / cnt;
    float var = B2[o] / cnt - mu * mu;
    float sc = dg[o] * rsqrtf(var + 1e-5f);
    bs[o] = sc;
    bb[o] = db[o] - mu * sc;
}

// ---------------- norm + mish + transpose (fp16 out, optional fp32 out) ------
__global__ void norm_transpose_kernel(const float* __restrict__ y,
                                      const float* __restrict__ scale,
                                      const float* __restrict__ shift,
                                      float* __restrict__ out_full,
                                      __half* __restrict__ out_hi)
{
    __shared__ float tile[CO][33];
    __shared__ float sc[CO], sh[CO];
    int n = blockIdx.y, l0 = blockIdx.x * 32;
    int tid = threadIdx.x;
    if (tid < CO) { sc[tid] = scale[n * CO + tid]; sh[tid] = shift[n * CO + tid]; }
    __syncthreads();
    int lt = tid & 31, ob = tid >> 5;
#pragma unroll
    for (int r = 0; r < 16; r++) {
        int o = ob + 8 * r;
        float v = y[((size_t)(n * CO + o)) * LL + l0 + lt];
        tile[o][lt] = mishf(v * sc[o] + sh[o]);
    }
    __syncthreads();
    int oc = tid & 127, lb = tid >> 7;
#pragma unroll
    for (int ly = lb; ly < 32; ly += 2) {
        size_t idx = ((size_t)n * LL + l0 + ly) * CO + oc;
        float v = tile[oc][ly];
        if (out_full) out_full[idx] = v;
        out_hi[idx] = __float2half_rn(v);
    }
}

// ---------------- batch-norm apply ----------------
__global__ void bn_apply_kernel(const float* __restrict__ xd,
                                const float* __restrict__ bs,
                                const float* __restrict__ bb,
                                float* __restrict__ out)
{
    size_t i4 = (size_t)blockIdx.x * 256 + threadIdx.x;
    const size_t total4 = (size_t)NN * CO * LO / 4;
    if (i4 >= total4) return;
    float4 v = ((const float4*)xd)[i4];
    int o = (int)((i4 * 4 / LO) & (CO - 1));
    float sc = bs[o], sh = bb[o];
    float4 r;
    r.x = mishf(v.x * sc + sh);
    r.y = mishf(v.y * sc + sh);
    r.z = mishf(v.z * sc + sh);
    r.w = mishf(v.w * sc + sh);
    ((float4*)out)[i4] = r;
}

// ---------------- launch ----------------
extern "C" void kernel_launch(void* const* d_in, const int* in_sizes, int n_in,
                              void* d_out, int out_size)
{
    const float* x        = (const float*)d_in[0];
    const float* t        = (const float*)d_in[1];
    const float* l1_k5    = (const float*)d_in[2];
    const float* l1_k3    = (const float*)d_in[3];
    const float* l1_k1    = (const float*)d_in[4];
    const float* l1_a3    = (const float*)d_in[5];
    const float* l1_a5    = (const float*)d_in[6];
    const float* l1_gw    = (const float*)d_in[7];
    const float* l1_gb    = (const float*)d_in[8];
    const float* l1_gamma = (const float*)d_in[9];
    const float* l1_beta  = (const float*)d_in[10];
    const float* l2_k5    = (const float*)d_in[11];
    const float* l2_k3    = (const float*)d_in[12];
    const float* l2_k1    = (const float*)d_in[13];
    const float* l2_a3    = (const float*)d_in[14];
    const float* l2_a5    = (const float*)d_in[15];
    const float* l2_gw    = (const float*)d_in[16];
    const float* l2_gb    = (const float*)d_in[17];
    const float* l2_gamma = (const float*)d_in[18];
    const float* l2_beta  = (const float*)d_in[19];
    const float* dw       = (const float*)d_in[20];
    const float* dg       = (const float*)d_in[21];
    const float* db       = (const float*)d_in[22];

    float* out      = (float*)d_out;
    float* out_xd   = out;
    float* out_skip = out + (size_t)NN * CO * LO;

    __half *xh, *hh, *ssh, *w1h, *w2h, *wdh, *wdl;
    float *ybuf, *xdbuf, *scl, *shf, *bsc, *bsh, *s1, *s2, *b1, *b2;
    cudaGetSymbolAddress((void**)&xh, g_xh);
    cudaGetSymbolAddress((void**)&hh, g_hh);
    cudaGetSymbolAddress((void**)&ssh, g_ssh);
    cudaGetSymbolAddress((void**)&ybuf, g_y);
    cudaGetSymbolAddress((void**)&w1h, g_w1h);
    cudaGetSymbolAddress((void**)&w2h, g_w2h);
    cudaGetSymbolAddress((void**)&wdh, g_wdh);
    cudaGetSymbolAddress((void**)&wdl, g_wdl);
    cudaGetSymbolAddress((void**)&xdbuf, g_xd);
    cudaGetSymbolAddress((void**)&scl, g_scale);
    cudaGetSymbolAddress((void**)&shf, g_shift);
    cudaGetSymbolAddress((void**)&bsc, g_bscale);
    cudaGetSymbolAddress((void**)&bsh, g_bshift);
    cudaGetSymbolAddress((void**)&s1, g_s1);
    cudaGetSymbolAddress((void**)&s2, g_s2);
    cudaGetSymbolAddress((void**)&b1, g_b1);
    cudaGetSymbolAddress((void**)&b2, g_b2);

    // smem: XT + 2 W buffers (hi only for conv1/2; hi+lo for down)
    const int SM1 = 132 * 144 + 2 * 9216;   // 37440
    const int SM2 = 132 * 272 + 2 * 9216;   // 54336
    const int SMD = 256 * 272 + 4 * 9216;   // 106496
    cudaFuncSetAttribute((const void*)mma_conv<64, 5, 1, 4, 128, true, false>,
                         cudaFuncAttributeMaxDynamicSharedMemorySize, SM1);
    cudaFuncSetAttribute((const void*)mma_conv<128, 5, 1, 4, 128, true, false>,
                         cudaFuncAttributeMaxDynamicSharedMemorySize, SM2);
    cudaFuncSetAttribute((const void*)mma_conv<128, 2, 2, 0, 128, false, true>,
                         cudaFuncAttributeMaxDynamicSharedMemorySize, SMD);

    // x -> fp16
    {
        size_t c4 = (size_t)NN * LL * CI1 / 4;
        split_x_kernel<<<(int)((c4 + 255) / 256), 256>>>(x, xh, c4);
    }

    // layer 1 (W hi-only)
    gate_weights_kernel<<<dim3(NN, CI1 / 64, 4), 512>>>(t, l1_gw, l1_gb, l1_k5, l1_k3, l1_k1,
                                                        l1_a3, l1_a5, w1h, nullptr, s1, s2, CI1);
    mma_conv<64, 5, 1, 4, 128, true, false><<<dim3(LL / 128, NN, 2), 256, SM1>>>(
        xh, w1h, nullptr, ybuf, s1, s2, (size_t)LL * CI1, (size_t)5 * 1 * CO * 64, LL);
    inorm_finalize<<<(NN * CO + 255) / 256, 256>>>(s1, s2, l1_gamma, l1_beta, scl, shf);
    norm_transpose_kernel<<<dim3(LL / 32, NN), 256>>>(ybuf, scl, shf, nullptr, hh);

    // layer 2 (W hi-only)
    gate_weights_kernel<<<dim3(NN, CO / 64, 4), 512>>>(t, l2_gw, l2_gb, l2_k5, l2_k3, l2_k1,
                                                       l2_a3, l2_a5, w2h, nullptr, s1, s2, CO);
    mma_conv<128, 5, 1, 4, 128, true, false><<<dim3(LL / 128, NN, 2), 256, SM2>>>(
        hh, w2h, nullptr, ybuf, s1, s2, (size_t)LL * CO, (size_t)5 * 2 * CO * 64, LL);
    inorm_finalize<<<(NN * CO + 255) / 256, 256>>>(s1, s2, l2_gamma, l2_beta, scl, shf);
    norm_transpose_kernel<<<dim3(LL / 32, NN), 256>>>(ybuf, scl, shf, out_skip, ssh);

    // downsample (keeps 2-term W) + BN + mish
    split_dw_kernel<<<(CO * 256 + 255) / 256, 256>>>(dw, wdh, wdl, b1, b2);
    mma_conv<128, 2, 2, 0, 128, false, true><<<dim3(LO / 128, NN, 2), 256, SMD>>>(
        ssh, wdh, wdl, xdbuf, b1, b2, (size_t)LL * CO, 0, LO);
    bn_finalize<<<1, 128>>>(b1, b2, dg, db, bsc, bsh);
    bn_apply_kernel<<<(int)(((size_t)NN * CO * LO / 4 + 255) / 256), 256>>>(xdbuf, bsc, bsh, out_xd);
}

// round 11
// speedup vs baseline: 1.6458x; 1.0139x over previous
#include <cuda_runtime.h>
#include <cuda_fp16.h>
#include <math.h>
#include <stdint.h>

#define NN 32
#define LL 8192
#define CO 128
#define CI1 64
#define TT 10
#define LO 4096

// ---------------- scratch (__device__ globals; no allocation) ----------------
__device__ __align__(128) __half g_xh[(size_t)NN * LL * CI1];
__device__ __align__(128) __half g_hh[(size_t)NN * LL * CO];
__device__ __align__(128) __half g_ssh[(size_t)NN * LL * CO];
__device__ __align__(128) __half g_y[(size_t)NN * CO * LL];     // conv out, fp16
__device__ __align__(128) float g_xd[(size_t)NN * CO * LO];     // down out, fp32
__device__ __align__(128) __half g_w1h[(size_t)NN * 5 * 1 * CO * 64];
__device__ __align__(128) __half g_w2h[(size_t)NN * 5 * 2 * CO * 64];
__device__ __align__(128) __half g_wdh[4 * CO * 64];
__device__ float g_s1[NN * CO];
__device__ float g_s2[NN * CO];
__device__ float g_b1[CO];
__device__ float g_b2[CO];
__device__ float g_scale[NN * CO];
__device__ float g_shift[NN * CO];
__device__ float g_bscale[CO];
__device__ float g_bshift[CO];

// ---------------- small device helpers ----------------
__device__ __forceinline__ float mishf(float v) {
    float sp = (v > 20.f) ? v : log1pf(expf(v));
    return v * tanhf(sp);
}
__device__ __forceinline__ uint32_t smem_u32(const void* p) {
    uint32_t a;
    asm("{ .reg .u64 t; cvta.to.shared.u64 t, %1; cvt.u32.u64 %0, t; }" : "=r"(a) : "l"(p));
    return a;
}
__device__ __forceinline__ void cp16(uint32_t dst, const void* src) {
    asm volatile("cp.async.cg.shared.global [%0], [%1], 16;" :: "r"(dst), "l"(src));
}
__device__ __forceinline__ void cp_commit() {
    asm volatile("cp.async.commit_group;" ::: "memory");
}
template <int N>
__device__ __forceinline__ void cp_wait() {
    asm volatile("cp.async.wait_group %0;" :: "n"(N) : "memory");
}
__device__ __forceinline__ void ldsm4(uint32_t* r, uint32_t addr) {
    asm volatile("ldmatrix.sync.aligned.m8n8.x4.shared.b16 {%0,%1,%2,%3}, [%4];"
                 : "=r"(r[0]), "=r"(r[1]), "=r"(r[2]), "=r"(r[3]) : "r"(addr));
}
__device__ __forceinline__ void mma_f16(float* d, const uint32_t* a, const uint32_t* b) {
    asm volatile("mma.sync.aligned.m16n8k16.row.col.f32.f16.f16.f32 "
                 "{%0,%1,%2,%3}, {%4,%5,%6,%7}, {%8,%9}, {%0,%1,%2,%3};"
                 : "+f"(d[0]), "+f"(d[1]), "+f"(d[2]), "+f"(d[3])
                 : "r"(a[0]), "r"(a[1]), "r"(a[2]), "r"(a[3]), "r"(b[0]), "r"(b[1]));
}

// ============================================================================
// Conv-as-GEMM, warp-level fp16 MMA (single-term W). Output type YT templated:
// __half (layers 1/2, norm applied later) or float (downsample, fp32 for BN).
// CTA = 256 threads (8 warps, 2x4), tile M=64 (o-half via blockIdx.z) x NT=128.
//   Y[n, o, l0+j] = sum_{k<NSHIFT, i<CI} W[n,o,i,k] * X[n, RS*(l0+j)+k-HALO, i]
// Fused per-(n,o) (or per-o) sum/sumsq stats via shuffle + atomics.
// ============================================================================
template <int CI, int NSHIFT, int RS, int HALO, int NT, bool PER_N_STATS, typename YT>
__global__ void __launch_bounds__(256, 3)
mma_conv(const __half* __restrict__ X,
         const __half* __restrict__ Wh,
         YT* __restrict__ Y, float* __restrict__ S1, float* __restrict__ S2,
         size_t x_nstride, size_t w_nstride, int outL)
{
    constexpr int HF = CI / 64;
    constexpr int P = NSHIFT * HF;
    constexpr int XR = NT * RS + HALO;
    constexpr int XPITCH = CI * 2 + 16;      // bytes; row step ≡ 4 banks (mod 32)
    constexpr int WPITCH = 144;
    constexpr int WCH = 64 * WPITCH;         // 64-row W chunk (this CTA's o-half)
    constexpr int XT = XR * XPITCH;
    constexpr int SEGR = CI / 8;
    constexpr int NB = NT / 64;
    constexpr int NFR = 2 * NB;

    extern __shared__ char sm[];
    const uint32_t base = smem_u32(sm);
    const uint32_t x_s = base;
    const uint32_t w_s = base + XT;

    const int tid = threadIdx.x;
    const int n = blockIdx.y;
    const int l0 = blockIdx.x * NT;
    const int o_base = blockIdx.z * 64;

    if (HALO > 0 && blockIdx.x == 0) {
        const uint4 z = make_uint4(0, 0, 0, 0);
        for (int s = tid; s < HALO * SEGR; s += 256) {
            int r = s / SEGR, c = s % SEGR;
            *(uint4*)(sm + r * XPITCH + c * 16) = z;
        }
    }
    {   // X tile
        const __half* gx = X + (size_t)n * x_nstride;
        for (int s = tid; s < XR * SEGR; s += 256) {
            int r = s / SEGR, c = s % SEGR;
            long l = (long)l0 * RS - HALO + r;
            if (l >= 0)
                cp16(x_s + r * XPITCH + c * 16, gx + (size_t)l * CI + (size_t)c * 8);
        }
    }
    auto load_w = [&](int piece, int buf) {
        const __half* ph = Wh + (size_t)n * w_nstride + (size_t)piece * (CO * 64)
                           + (size_t)o_base * 64;
        uint32_t dst = w_s + (uint32_t)buf * WCH;
        for (int s = tid; s < 512; s += 256) {
            int r = s >> 3, c = s & 7;
            cp16(dst + r * WPITCH + c * 16, ph + r * 64 + c * 8);
        }
        cp_commit();
    };
    load_w(0, 0);

    const int warp = tid >> 5, lane = tid & 31;
    const int o0w = (warp >> 2) * 32;
    const int n0w = (warp & 3) * (NT / 4);
    const int a_row = (lane & 7) + ((lane >> 3) & 1) * 8;
    const int a_csh = (lane >> 4) * 8;
    const int b_jj = (lane & 7) + ((lane >> 4) << 3);
    const int b_csh = ((lane >> 3) & 1) * 8;

    float acc[2][NFR][4];
#pragma unroll
    for (int mi = 0; mi < 2; mi++)
#pragma unroll
        for (int nf = 0; nf < NFR; nf++)
#pragma unroll
            for (int q = 0; q < 4; q++) acc[mi][nf][q] = 0.f;

    for (int p = 0; p < P; p++) {
        cp_wait<0>();
        __syncthreads();   // readers of buffer (p+1)&1 (= piece p-1) are done
        if (p + 1 < P) load_w(p + 1, (p + 1) & 1);

        const int k = p / HF, hf = p % HF;
        const uint32_t wh_b = w_s + (uint32_t)(p & 1) * WCH;

#pragma unroll
        for (int i16 = 0; i16 < 4; i16++) {
            const int i0 = i16 * 16;
            uint32_t Ah[2][4];
#pragma unroll
            for (int mi = 0; mi < 2; mi++) {
                uint32_t ao = (uint32_t)((o0w + a_row + mi * 16) * WPITCH + (i0 + a_csh) * 2);
                ldsm4(Ah[mi], wh_b + ao);
            }
            const int xcol = (hf * 64 + i0 + b_csh) * 2;
#pragma unroll
            for (int nb = 0; nb < NB; nb++) {
                uint32_t B[4];
                uint32_t xo = (uint32_t)((RS * (n0w + nb * 16 + b_jj) + k) * XPITCH + xcol);
                ldsm4(B, x_s + xo);
#pragma unroll
                for (int mi = 0; mi < 2; mi++)
#pragma unroll
                    for (int hl = 0; hl < 2; hl++)
                        mma_f16(acc[mi][nb * 2 + hl], Ah[mi], &B[hl * 2]);
            }
        }
    }

    // ---------------- epilogue: store (fp16 or fp32) + fused stats ----------------
    const int g = lane >> 2, tg = lane & 3;
#pragma unroll
    for (int mi = 0; mi < 2; mi++) {
        const int o = o_base + o0w + mi * 16 + g;
        YT* row0 = Y + ((size_t)(n * CO + o)) * outL + l0 + n0w;
        YT* row1 = row0 + (size_t)8 * outL;
#pragma unroll
        for (int nf = 0; nf < NFR; nf++) {
            int c = nf * 8 + tg * 2;
            if (sizeof(YT) == 2) {
                *(__half2*)((__half*)row0 + c) = __floats2half2_rn(acc[mi][nf][0], acc[mi][nf][1]);
                *(__half2*)((__half*)row1 + c) = __floats2half2_rn(acc[mi][nf][2], acc[mi][nf][3]);
            } else {
                *(float2*)((float*)row0 + c) = make_float2(acc[mi][nf][0], acc[mi][nf][1]);
                *(float2*)((float*)row1 + c) = make_float2(acc[mi][nf][2], acc[mi][nf][3]);
            }
        }
    }
    float ts[4], tq[4];
#pragma unroll
    for (int r = 0; r < 4; r++) { ts[r] = 0.f; tq[r] = 0.f; }
#pragma unroll
    for (int mi = 0; mi < 2; mi++)
#pragma unroll
        for (int nf = 0; nf < NFR; nf++) {
            float a0 = acc[mi][nf][0], a1 = acc[mi][nf][1];
            float a2 = acc[mi][nf][2], a3 = acc[mi][nf][3];
            ts[2 * mi]     += a0 + a1;  tq[2 * mi]     += a0 * a0 + a1 * a1;
            ts[2 * mi + 1] += a2 + a3;  tq[2 * mi + 1] += a2 * a2 + a3 * a3;
        }
#pragma unroll
    for (int r = 0; r < 4; r++) {
        ts[r] += __shfl_xor_sync(0xffffffffu, ts[r], 1);
        ts[r] += __shfl_xor_sync(0xffffffffu, ts[r], 2);
        tq[r] += __shfl_xor_sync(0xffffffffu, tq[r], 1);
        tq[r] += __shfl_xor_sync(0xffffffffu, tq[r], 2);
    }
    if (tg == 0) {
        const int sbase = PER_N_STATS ? n * CO : 0;
#pragma unroll
        for (int r = 0; r < 4; r++) {
            int o = o_base + o0w + (r >> 1) * 16 + g + (r & 1) * 8;
            atomicAdd(&S1[sbase + o], ts[r]);
            atomicAdd(&S2[sbase + o], tq[r]);
        }
    }
}

// ---------------- fp32 -> fp16 ----------------
__global__ void split_x_kernel(const float* __restrict__ src,
                               __half* __restrict__ hi, size_t count4)
{
    size_t i = (size_t)blockIdx.x * 256 + threadIdx.x;
    if (i >= count4) return;
    float4 v = ((const float4*)src)[i];
    ((__half2*)hi)[2 * i]     = __floats2half2_rn(v.x, v.y);
    ((__half2*)hi)[2 * i + 1] = __floats2half2_rn(v.z, v.w);
}

// ---------------- gate + per-sample weights (fp16) ----------------
// grid (NN, HF, 4), block 512 = 8 o-lanes x 64 ii-lanes.
__global__ void __launch_bounds__(512)
gate_weights_kernel(const float* __restrict__ t,
                    const float* __restrict__ gw,
                    const float* __restrict__ gb,
                    const float* __restrict__ k5,
                    const float* __restrict__ k3,
                    const float* __restrict__ k1,
                    const float* __restrict__ a3,
                    const float* __restrict__ a5,
                    __half* __restrict__ wh,
                    float* __restrict__ S1, float* __restrict__ S2,
                    int CI)
{
    const int n = blockIdx.x;
    const int hf = blockIdx.y;
    const int HF = gridDim.y;
    const int oc = blockIdx.z;
    const int tid = threadIdx.x;

    __shared__ float gs[5][128];
    if (tid < 128) {
        const int o = tid;
        if (blockIdx.y == 0 && blockIdx.z == 0) {
            S1[n * CO + o] = 0.f;
            S2[n * CO + o] = 0.f;
        }
        float tv[TT];
#pragma unroll
        for (int j = 0; j < TT; j++) tv[j] = t[n * TT + j];
        float g[5];
        float mx = -1e30f;
#pragma unroll
        for (int e = 0; e < 5; e++) {
            float s = gb[e * CO + o];
            const float* gwr = gw + (size_t)(e * CO + o) * TT;
#pragma unroll
            for (int j = 0; j < TT; j++) s += tv[j] * gwr[j];
            g[e] = s;
            mx = fmaxf(mx, s);
        }
        float den = 0.f;
#pragma unroll
        for (int e = 0; e < 5; e++) { g[e] = expf(g[e] - mx); den += g[e]; }
        float inv = 1.f / den;
        gs[0][o] = g[0] * inv;
        gs[1][o] = g[1] * inv;
        gs[2][o] = g[2] * inv;
        gs[3][o] = g[3] * inv * (1.f / 3.f);
        gs[4][o] = g[4] * inv * 0.2f;
    }
    __syncthreads();

    const int og = tid >> 6;
    const int ii = tid & 63;
    const int i = hf * 64 + ii;
    const size_t kstride = (size_t)HF * 128 * 64;

#pragma unroll
    for (int oj = 0; oj < 4; oj++) {
        const int o = oc * 32 + oj * 8 + og;
        const float g0 = gs[0][o], g1 = gs[1][o], g2 = gs[2][o];
        const float g3v = gs[3][o], g4v = gs[4][o];
        const int oi = o * CI + i;
        const float* p5 = k5 + (size_t)oi * 5;
        const float* p3 = k3 + (size_t)oi * 3;
        const float bse = g4v * a5[oi];
        const float c3v = g3v * a3[oi];
        float wv[5];
        wv[0] = g0 * p5[0] + bse;
        wv[1] = g0 * p5[1] + bse;
        wv[2] = g0 * p5[2] + g1 * p3[0] + c3v + bse;
        wv[3] = g0 * p5[3] + g1 * p3[1] + c3v + bse;
        wv[4] = g0 * p5[4] + g1 * p3[2] + c3v + g2 * k1[oi] + bse;
        const size_t idx0 = (((size_t)n * 5 * HF + hf) * 128 + o) * 64 + ii;
#pragma unroll
        for (int k = 0; k < 5; k++)
            wh[idx0 + k * kstride] = __float2half_rn(wv[k]);
    }
}

// ---------------- downsample weight reorder (+ zero bn accums) -------
__global__ void split_dw_kernel(const float* __restrict__ dw,
                                __half* __restrict__ wdh,
                                float* __restrict__ B1, float* __restrict__ B2)
{
    int idx = blockIdx.x * 256 + threadIdx.x;
    if (blockIdx.x == 0) {
        if (threadIdx.x < CO) B1[threadIdx.x] = 0.f;
        else B2[threadIdx.x - CO] = 0.f;
    }
    if (idx >= CO * 256) return;
    int o = idx >> 8, r = idx & 255;
    int kk = r >> 7, ifull = r & 127;
    float v = dw[(size_t)o * 256 + ifull * 2 + kk];
    size_t out = (((size_t)kk * 2 + (ifull >> 6)) * 128 + o) * 64 + (ifull & 63);
    wdh[out] = __float2half_rn(v);
}

// ---------------- finalize kernels ----------------
__global__ void inorm_finalize(const float* __restrict__ S1, const float* __restrict__ S2,
                               const float* __restrict__ gamma, const float* __restrict__ beta,
                               float* __restrict__ scale, float* __restrict__ shift)
{
    int no = blockIdx.x * 256 + threadIdx.x;
    if (no >= NN * CO) return;
    int o = no & (CO - 1);
    float mu = S1[no] * (1.f / LL);
    float var = S2[no] * (1.f / LL) - mu * mu;
    float sc = gamma[o] * rsqrtf(var + 1e-5f);
    scale[no] = sc;
    shift[no] = beta[o] - mu * sc;
}

__global__ void bn_finalize(const float* __restrict__ B1, const float* __restrict__ B2,
                            const float* __restrict__ dg, const float* __restrict__ db,
                            float* __restrict__ bs, float* __restrict__ bb)
{
    int o = threadIdx.x;
    if (o >= CO) return;
    const float cnt = (float)NN * LO;
    float mu = B1[o] / cnt;
    float var = B2[o] / cnt - mu * mu;
    float sc = dg[o] * rsqrtf(var + 1e-5f);
    bs[o] = sc;
    bb[o] = db[o] - mu * sc;
}

// ---------------- norm + mish + transpose (fp16 in, fp16 out, opt fp32) ------
__global__ void norm_transpose_kernel(const __half* __restrict__ y,
                                      const float* __restrict__ scale,
                                      const float* __restrict__ shift,
                                      float* __restrict__ out_full,
                                      __half* __restrict__ out_hi)
{
    __shared__ float tile[CO][33];
    __shared__ float sc[CO], sh[CO];
    int n = blockIdx.y, l0 = blockIdx.x * 32;
    int tid = threadIdx.x;
    if (tid < CO) { sc[tid] = scale[n * CO + tid]; sh[tid] = shift[n * CO + tid]; }
    __syncthreads();
    int lt = tid & 31, ob = tid >> 5;
#pragma unroll
    for (int r = 0; r < 16; r++) {
        int o = ob + 8 * r;
        float v = __half2float(y[((size_t)(n * CO + o)) * LL + l0 + lt]);
        tile[o][lt] = mishf(v * sc[o] + sh[o]);
    }
    __syncthreads();
    int oc = tid & 127, lb = tid >> 7;
#pragma unroll
    for (int ly = lb; ly < 32; ly += 2) {
        size_t idx = ((size_t)n * LL + l0 + ly) * CO + oc;
        float v = tile[oc][ly];
        if (out_full) out_full[idx] = v;
        out_hi[idx] = __float2half_rn(v);
    }
}

// ---------------- batch-norm apply ----------------
__global__ void bn_apply_kernel(const float* __restrict__ xd,
                                const float* __restrict__ bs,
                                const float* __restrict__ bb,
                                float* __restrict__ out)
{
    size_t i4 = (size_t)blockIdx.x * 256 + threadIdx.x;
    const size_t total4 = (size_t)NN * CO * LO / 4;
    if (i4 >= total4) return;
    float4 v = ((const float4*)xd)[i4];
    int o = (int)((i4 * 4 / LO) & (CO - 1));
    float sc = bs[o], sh = bb[o];
    float4 r;
    r.x = mishf(v.x * sc + sh);
    r.y = mishf(v.y * sc + sh);
    r.z = mishf(v.z * sc + sh);
    r.w = mishf(v.w * sc + sh);
    ((float4*)out)[i4] = r;
}

// ---------------- launch ----------------
extern "C" void kernel_launch(void* const* d_in, const int* in_sizes, int n_in,
                              void* d_out, int out_size)
{
    const float* x        = (const float*)d_in[0];
    const float* t        = (const float*)d_in[1];
    const float* l1_k5    = (const float*)d_in[2];
    const float* l1_k3    = (const float*)d_in[3];
    const float* l1_k1    = (const float*)d_in[4];
    const float* l1_a3    = (const float*)d_in[5];
    const float* l1_a5    = (const float*)d_in[6];
    const float* l1_gw    = (const float*)d_in[7];
    const float* l1_gb    = (const float*)d_in[8];
    const float* l1_gamma = (const float*)d_in[9];
    const float* l1_beta  = (const float*)d_in[10];
    const float* l2_k5    = (const float*)d_in[11];
    const float* l2_k3    = (const float*)d_in[12];
    const float* l2_k1    = (const float*)d_in[13];
    const float* l2_a3    = (const float*)d_in[14];
    const float* l2_a5    = (const float*)d_in[15];
    const float* l2_gw    = (const float*)d_in[16];
    const float* l2_gb    = (const float*)d_in[17];
    const float* l2_gamma = (const float*)d_in[18];
    const float* l2_beta  = (const float*)d_in[19];
    const float* dw       = (const float*)d_in[20];
    const float* dg       = (const float*)d_in[21];
    const float* db       = (const float*)d_in[22];

    float* out      = (float*)d_out;
    float* out_xd   = out;
    float* out_skip = out + (size_t)NN * CO * LO;

    __half *xh, *hh, *ssh, *ybuf, *w1h, *w2h, *wdh;
    float *xdbuf, *scl, *shf, *bsc, *bsh, *s1, *s2, *b1, *b2;
    cudaGetSymbolAddress((void**)&xh, g_xh);
    cudaGetSymbolAddress((void**)&hh, g_hh);
    cudaGetSymbolAddress((void**)&ssh, g_ssh);
    cudaGetSymbolAddress((void**)&ybuf, g_y);
    cudaGetSymbolAddress((void**)&w1h, g_w1h);
    cudaGetSymbolAddress((void**)&w2h, g_w2h);
    cudaGetSymbolAddress((void**)&wdh, g_wdh);
    cudaGetSymbolAddress((void**)&xdbuf, g_xd);
    cudaGetSymbolAddress((void**)&scl, g_scale);
    cudaGetSymbolAddress((void**)&shf, g_shift);
    cudaGetSymbolAddress((void**)&bsc, g_bscale);
    cudaGetSymbolAddress((void**)&bsh, g_bshift);
    cudaGetSymbolAddress((void**)&s1, g_s1);
    cudaGetSymbolAddress((void**)&s2, g_s2);
    cudaGetSymbolAddress((void**)&b1, g_b1);
    cudaGetSymbolAddress((void**)&b2, g_b2);

    // smem: XT + 2 W buffers (hi only)
    const int SM1 = 132 * 144 + 2 * 9216;   // 37440
    const int SM2 = 132 * 272 + 2 * 9216;   // 54336
    const int SMD = 256 * 272 + 2 * 9216;   // 88064
    cudaFuncSetAttribute((const void*)mma_conv<64, 5, 1, 4, 128, true, __half>,
                         cudaFuncAttributeMaxDynamicSharedMemorySize, SM1);
    cudaFuncSetAttribute((const void*)mma_conv<128, 5, 1, 4, 128, true, __half>,
                         cudaFuncAttributeMaxDynamicSharedMemorySize, SM2);
    cudaFuncSetAttribute((const void*)mma_conv<128, 2, 2, 0, 128, false, float>,
                         cudaFuncAttributeMaxDynamicSharedMemorySize, SMD);

    // x -> fp16
    {
        size_t c4 = (size_t)NN * LL * CI1 / 4;
        split_x_kernel<<<(int)((c4 + 255) / 256), 256>>>(x, xh, c4);
    }

    // layer 1
    gate_weights_kernel<<<dim3(NN, CI1 / 64, 4), 512>>>(t, l1_gw, l1_gb, l1_k5, l1_k3, l1_k1,
                                                        l1_a3, l1_a5, w1h, s1, s2, CI1);
    mma_conv<64, 5, 1, 4, 128, true, __half><<<dim3(LL / 128, NN, 2), 256, SM1>>>(
        xh, w1h, ybuf, s1, s2, (size_t)LL * CI1, (size_t)5 * 1 * CO * 64, LL);
    inorm_finalize<<<(NN * CO + 255) / 256, 256>>>(s1, s2, l1_gamma, l1_beta, scl, shf);
    norm_transpose_kernel<<<dim3(LL / 32, NN), 256>>>(ybuf, scl, shf, nullptr, hh);

    // layer 2
    gate_weights_kernel<<<dim3(NN, CO / 64, 4), 512>>>(t, l2_gw, l2_gb, l2_k5, l2_k3, l2_k1,
                                                       l2_a3, l2_a5, w2h, s1, s2, CO);
    mma_conv<128, 5, 1, 4, 128, true, __half><<<dim3(LL / 128, NN, 2), 256, SM2>>>(
        hh, w2h, ybuf, s1, s2, (size_t)LL * CO, (size_t)5 * 2 * CO * 64, LL);
    inorm_finalize<<<(NN * CO + 255) / 256, 256>>>(s1, s2, l2_gamma, l2_beta, scl, shf);
    norm_transpose_kernel<<<dim3(LL / 32, NN), 256>>>(ybuf, scl, shf, out_skip, ssh);

    // downsample (one-term W) + BN + mish
    split_dw_kernel<<<(CO * 256 + 255) / 256, 256>>>(dw, wdh, b1, b2);
    mma_conv<128, 2, 2, 0, 128, false, float><<<dim3(LO / 128, NN, 2), 256, SMD>>>(
        ssh, wdh, xdbuf, b1, b2, (size_t)LL * CO, 0, LO);
    bn_finalize<<<1, 128>>>(b1, b2, dg, db, bsc, bsh);
    bn_apply_kernel<<<(int)(((size_t)NN * CO * LO / 4 + 255) / 256), 256>>>(xdbuf, bsc, bsh, out_xd);
}

// round 12
// speedup vs baseline: 1.6922x; 1.0282x over previous
#include <cuda_runtime.h>
#include <cuda_fp16.h>
#include <math.h>
#include <stdint.h>

#define NN 32
#define LL 8192
#define CO 128
#define CI1 64
#define TT 10
#define LO 4096

// ---------------- scratch (__device__ globals; no allocation) ----------------
__device__ __align__(128) __half g_xh[(size_t)NN * LL * CI1];
__device__ __align__(128) __half g_hh[(size_t)NN * LL * CO];
__device__ __align__(128) __half g_ssh[(size_t)NN * LL * CO];
__device__ __align__(128) __half g_y[(size_t)NN * CO * LL];
__device__ __align__(128) float g_xd[(size_t)NN * CO * LO];
__device__ __align__(128) __half g_w1h[(size_t)NN * 5 * 1 * CO * 64];
__device__ __align__(128) __half g_w2h[(size_t)NN * 5 * 2 * CO * 64];
__device__ __align__(128) __half g_wdh[4 * CO * 64];
__device__ float g_s1[NN * CO];
__device__ float g_s2[NN * CO];
__device__ float g_b1[CO];
__device__ float g_b2[CO];

// ---------------- small device helpers ----------------
__device__ __forceinline__ float mishf(float v) {
    float sp = (v > 20.f) ? v : log1pf(expf(v));
    return v * tanhf(sp);
}
__device__ __forceinline__ uint32_t smem_u32(const void* p) {
    uint32_t a;
    asm("{ .reg .u64 t; cvta.to.shared.u64 t, %1; cvt.u32.u64 %0, t; }" : "=r"(a) : "l"(p));
    return a;
}
__device__ __forceinline__ void cp16(uint32_t dst, const void* src) {
    asm volatile("cp.async.cg.shared.global [%0], [%1], 16;" :: "r"(dst), "l"(src));
}
__device__ __forceinline__ void cp_commit() {
    asm volatile("cp.async.commit_group;" ::: "memory");
}
template <int N>
__device__ __forceinline__ void cp_wait() {
    asm volatile("cp.async.wait_group %0;" :: "n"(N) : "memory");
}
__device__ __forceinline__ void ldsm4(uint32_t* r, uint32_t addr) {
    asm volatile("ldmatrix.sync.aligned.m8n8.x4.shared.b16 {%0,%1,%2,%3}, [%4];"
                 : "=r"(r[0]), "=r"(r[1]), "=r"(r[2]), "=r"(r[3]) : "r"(addr));
}
__device__ __forceinline__ void mma_f16(float* d, const uint32_t* a, const uint32_t* b) {
    asm volatile("mma.sync.aligned.m16n8k16.row.col.f32.f16.f16.f32 "
                 "{%0,%1,%2,%3}, {%4,%5,%6,%7}, {%8,%9}, {%0,%1,%2,%3};"
                 : "+f"(d[0]), "+f"(d[1]), "+f"(d[2]), "+f"(d[3])
                 : "r"(a[0]), "r"(a[1]), "r"(a[2]), "r"(a[3]), "r"(b[0]), "r"(b[1]));
}

// ============================================================================
// Conv-as-GEMM, warp-level fp16 MMA (single fp16 W).
// CTA = 256 threads (8 warps, 2x4); tile M=64 (o-half, blockIdx.z) x NT.
// NT=256 for conv1/2 (warp tile 32x64 -> fewer LDSM per MMA, half the CTAs),
// NT=128 for downsample. Output YT = __half or float. Fused stats.
// ============================================================================
template <int CI, int NSHIFT, int RS, int HALO, int NT, bool PER_N_STATS, typename YT>
__global__ void __launch_bounds__(256, 2)
mma_conv(const __half* __restrict__ X,
         const __half* __restrict__ Wh,
         YT* __restrict__ Y, float* __restrict__ S1, float* __restrict__ S2,
         size_t x_nstride, size_t w_nstride, int outL)
{
    constexpr int HF = CI / 64;
    constexpr int P = NSHIFT * HF;
    constexpr int XR = NT * RS + HALO;
    constexpr int XPITCH = CI * 2 + 16;      // bytes; row step ≡ 4 banks (mod 32)
    constexpr int WPITCH = 144;
    constexpr int WCH = 64 * WPITCH;         // 64-row W chunk (this CTA's o-half)
    constexpr int XT = XR * XPITCH;
    constexpr int SEGR = CI / 8;
    constexpr int NB = NT / 64;              // 16-col blocks per warp
    constexpr int NFR = 2 * NB;

    extern __shared__ char sm[];
    const uint32_t base = smem_u32(sm);
    const uint32_t x_s = base;
    const uint32_t w_s = base + XT;

    const int tid = threadIdx.x;
    const int n = blockIdx.y;
    const int l0 = blockIdx.x * NT;
    const int o_base = blockIdx.z * 64;

    if (HALO > 0 && blockIdx.x == 0) {
        const uint4 z = make_uint4(0, 0, 0, 0);
        for (int s = tid; s < HALO * SEGR; s += 256) {
            int r = s / SEGR, c = s % SEGR;
            *(uint4*)(sm + r * XPITCH + c * 16) = z;
        }
    }
    {   // X tile
        const __half* gx = X + (size_t)n * x_nstride;
        for (int s = tid; s < XR * SEGR; s += 256) {
            int r = s / SEGR, c = s % SEGR;
            long l = (long)l0 * RS - HALO + r;
            if (l >= 0)
                cp16(x_s + r * XPITCH + c * 16, gx + (size_t)l * CI + (size_t)c * 8);
        }
    }
    auto load_w = [&](int piece, int buf) {
        const __half* ph = Wh + (size_t)n * w_nstride + (size_t)piece * (CO * 64)
                           + (size_t)o_base * 64;
        uint32_t dst = w_s + (uint32_t)buf * WCH;
        for (int s = tid; s < 512; s += 256) {
            int r = s >> 3, c = s & 7;
            cp16(dst + r * WPITCH + c * 16, ph + r * 64 + c * 8);
        }
        cp_commit();
    };
    load_w(0, 0);

    const int warp = tid >> 5, lane = tid & 31;
    const int o0w = (warp >> 2) * 32;
    const int n0w = (warp & 3) * (NT / 4);
    const int a_row = (lane & 7) + ((lane >> 3) & 1) * 8;
    const int a_csh = (lane >> 4) * 8;
    const int b_jj = (lane & 7) + ((lane >> 4) << 3);
    const int b_csh = ((lane >> 3) & 1) * 8;

    float acc[2][NFR][4];
#pragma unroll
    for (int mi = 0; mi < 2; mi++)
#pragma unroll
        for (int nf = 0; nf < NFR; nf++)
#pragma unroll
            for (int q = 0; q < 4; q++) acc[mi][nf][q] = 0.f;

    for (int p = 0; p < P; p++) {
        cp_wait<0>();
        __syncthreads();   // readers of buffer (p+1)&1 (= piece p-1) are done
        if (p + 1 < P) load_w(p + 1, (p + 1) & 1);

        const int k = p / HF, hf = p % HF;
        const uint32_t wh_b = w_s + (uint32_t)(p & 1) * WCH;

#pragma unroll
        for (int i16 = 0; i16 < 4; i16++) {
            const int i0 = i16 * 16;
            uint32_t Ah[2][4];
#pragma unroll
            for (int mi = 0; mi < 2; mi++) {
                uint32_t ao = (uint32_t)((o0w + a_row + mi * 16) * WPITCH + (i0 + a_csh) * 2);
                ldsm4(Ah[mi], wh_b + ao);
            }
            const int xcol = (hf * 64 + i0 + b_csh) * 2;
#pragma unroll
            for (int nb = 0; nb < NB; nb++) {
                uint32_t B[4];
                uint32_t xo = (uint32_t)((RS * (n0w + nb * 16 + b_jj) + k) * XPITCH + xcol);
                ldsm4(B, x_s + xo);
#pragma unroll
                for (int mi = 0; mi < 2; mi++)
#pragma unroll
                    for (int hl = 0; hl < 2; hl++)
                        mma_f16(acc[mi][nb * 2 + hl], Ah[mi], &B[hl * 2]);
            }
        }
    }

    // ---------------- epilogue: store + fused stats ----------------
    const int g = lane >> 2, tg = lane & 3;
#pragma unroll
    for (int mi = 0; mi < 2; mi++) {
        const int o = o_base + o0w + mi * 16 + g;
        YT* row0 = Y + ((size_t)(n * CO + o)) * outL + l0 + n0w;
        YT* row1 = row0 + (size_t)8 * outL;
#pragma unroll
        for (int nf = 0; nf < NFR; nf++) {
            int c = nf * 8 + tg * 2;
            if (sizeof(YT) == 2) {
                *(__half2*)((__half*)row0 + c) = __floats2half2_rn(acc[mi][nf][0], acc[mi][nf][1]);
                *(__half2*)((__half*)row1 + c) = __floats2half2_rn(acc[mi][nf][2], acc[mi][nf][3]);
            } else {
                *(float2*)((float*)row0 + c) = make_float2(acc[mi][nf][0], acc[mi][nf][1]);
                *(float2*)((float*)row1 + c) = make_float2(acc[mi][nf][2], acc[mi][nf][3]);
            }
        }
    }
    float ts[4], tq[4];
#pragma unroll
    for (int r = 0; r < 4; r++) { ts[r] = 0.f; tq[r] = 0.f; }
#pragma unroll
    for (int mi = 0; mi < 2; mi++)
#pragma unroll
        for (int nf = 0; nf < NFR; nf++) {
            float a0 = acc[mi][nf][0], a1 = acc[mi][nf][1];
            float a2 = acc[mi][nf][2], a3 = acc[mi][nf][3];
            ts[2 * mi]     += a0 + a1;  tq[2 * mi]     += a0 * a0 + a1 * a1;
            ts[2 * mi + 1] += a2 + a3;  tq[2 * mi + 1] += a2 * a2 + a3 * a3;
        }
#pragma unroll
    for (int r = 0; r < 4; r++) {
        ts[r] += __shfl_xor_sync(0xffffffffu, ts[r], 1);
        ts[r] += __shfl_xor_sync(0xffffffffu, ts[r], 2);
        tq[r] += __shfl_xor_sync(0xffffffffu, tq[r], 1);
        tq[r] += __shfl_xor_sync(0xffffffffu, tq[r], 2);
    }
    if (tg == 0) {
        const int sbase = PER_N_STATS ? n * CO : 0;
#pragma unroll
        for (int r = 0; r < 4; r++) {
            int o = o_base + o0w + (r >> 1) * 16 + g + (r & 1) * 8;
            atomicAdd(&S1[sbase + o], ts[r]);
            atomicAdd(&S2[sbase + o], tq[r]);
        }
    }
}

// ---------------- fp32 -> fp16 ----------------
__global__ void split_x_kernel(const float* __restrict__ src,
                               __half* __restrict__ hi, size_t count4)
{
    size_t i = (size_t)blockIdx.x * 256 + threadIdx.x;
    if (i >= count4) return;
    float4 v = ((const float4*)src)[i];
    ((__half2*)hi)[2 * i]     = __floats2half2_rn(v.x, v.y);
    ((__half2*)hi)[2 * i + 1] = __floats2half2_rn(v.z, v.w);
}

// ---------------- gate + per-sample weights (fp16) ----------------
__global__ void __launch_bounds__(512)
gate_weights_kernel(const float* __restrict__ t,
                    const float* __restrict__ gw,
                    const float* __restrict__ gb,
                    const float* __restrict__ k5,
                    const float* __restrict__ k3,
                    const float* __restrict__ k1,
                    const float* __restrict__ a3,
                    const float* __restrict__ a5,
                    __half* __restrict__ wh,
                    float* __restrict__ S1, float* __restrict__ S2,
                    int CI)
{
    const int n = blockIdx.x;
    const int hf = blockIdx.y;
    const int HF = gridDim.y;
    const int oc = blockIdx.z;
    const int tid = threadIdx.x;

    __shared__ float gs[5][128];
    if (tid < 128) {
        const int o = tid;
        if (blockIdx.y == 0 && blockIdx.z == 0) {
            S1[n * CO + o] = 0.f;
            S2[n * CO + o] = 0.f;
        }
        float tv[TT];
#pragma unroll
        for (int j = 0; j < TT; j++) tv[j] = t[n * TT + j];
        float g[5];
        float mx = -1e30f;
#pragma unroll
        for (int e = 0; e < 5; e++) {
            float s = gb[e * CO + o];
            const float* gwr = gw + (size_t)(e * CO + o) * TT;
#pragma unroll
            for (int j = 0; j < TT; j++) s += tv[j] * gwr[j];
            g[e] = s;
            mx = fmaxf(mx, s);
        }
        float den = 0.f;
#pragma unroll
        for (int e = 0; e < 5; e++) { g[e] = expf(g[e] - mx); den += g[e]; }
        float inv = 1.f / den;
        gs[0][o] = g[0] * inv;
        gs[1][o] = g[1] * inv;
        gs[2][o] = g[2] * inv;
        gs[3][o] = g[3] * inv * (1.f / 3.f);
        gs[4][o] = g[4] * inv * 0.2f;
    }
    __syncthreads();

    const int og = tid >> 6;
    const int ii = tid & 63;
    const int i = hf * 64 + ii;
    const size_t kstride = (size_t)HF * 128 * 64;

#pragma unroll
    for (int oj = 0; oj < 4; oj++) {
        const int o = oc * 32 + oj * 8 + og;
        const float g0 = gs[0][o], g1 = gs[1][o], g2 = gs[2][o];
        const float g3v = gs[3][o], g4v = gs[4][o];
        const int oi = o * CI + i;
        const float* p5 = k5 + (size_t)oi * 5;
        const float* p3 = k3 + (size_t)oi * 3;
        const float bse = g4v * a5[oi];
        const float c3v = g3v * a3[oi];
        float wv[5];
        wv[0] = g0 * p5[0] + bse;
        wv[1] = g0 * p5[1] + bse;
        wv[2] = g0 * p5[2] + g1 * p3[0] + c3v + bse;
        wv[3] = g0 * p5[3] + g1 * p3[1] + c3v + bse;
        wv[4] = g0 * p5[4] + g1 * p3[2] + c3v + g2 * k1[oi] + bse;
        const size_t idx0 = (((size_t)n * 5 * HF + hf) * 128 + o) * 64 + ii;
#pragma unroll
        for (int k = 0; k < 5; k++)
            wh[idx0 + k * kstride] = __float2half_rn(wv[k]);
    }
}

// ---------------- downsample weight reorder (+ zero bn accums) -------
__global__ void split_dw_kernel(const float* __restrict__ dw,
                                __half* __restrict__ wdh,
                                float* __restrict__ B1, float* __restrict__ B2)
{
    int idx = blockIdx.x * 256 + threadIdx.x;
    if (blockIdx.x == 0) {
        if (threadIdx.x < CO) B1[threadIdx.x] = 0.f;
        else B2[threadIdx.x - CO] = 0.f;
    }
    if (idx >= CO * 256) return;
    int o = idx >> 8, r = idx & 255;
    int kk = r >> 7, ifull = r & 127;
    float v = dw[(size_t)o * 256 + ifull * 2 + kk];
    size_t out = (((size_t)kk * 2 + (ifull >> 6)) * 128 + o) * 64 + (ifull & 63);
    wdh[out] = __float2half_rn(v);
}

// ---------------- norm + mish + transpose (inorm finalize fused) ------------
__global__ void norm_transpose_kernel(const __half* __restrict__ y,
                                      const float* __restrict__ S1,
                                      const float* __restrict__ S2,
                                      const float* __restrict__ gamma,
                                      const float* __restrict__ beta,
                                      float* __restrict__ out_full,
                                      __half* __restrict__ out_hi)
{
    __shared__ float tile[CO][33];
    __shared__ float sc[CO], sh[CO];
    int n = blockIdx.y, l0 = blockIdx.x * 32;
    int tid = threadIdx.x;
    if (tid < CO) {
        int no = n * CO + tid;
        float mu = S1[no] * (1.f / LL);
        float var = S2[no] * (1.f / LL) - mu * mu;
        float s = gamma[tid] * rsqrtf(var + 1e-5f);
        sc[tid] = s;
        sh[tid] = beta[tid] - mu * s;
    }
    __syncthreads();
    int lt = tid & 31, ob = tid >> 5;
#pragma unroll
    for (int r = 0; r < 16; r++) {
        int o = ob + 8 * r;
        float v = __half2float(y[((size_t)(n * CO + o)) * LL + l0 + lt]);
        tile[o][lt] = mishf(v * sc[o] + sh[o]);
    }
    __syncthreads();
    int oc = tid & 127, lb = tid >> 7;
#pragma unroll
    for (int ly = lb; ly < 32; ly += 2) {
        size_t idx = ((size_t)n * LL + l0 + ly) * CO + oc;
        float v = tile[oc][ly];
        if (out_full) out_full[idx] = v;
        out_hi[idx] = __float2half_rn(v);
    }
}

// ---------------- batch-norm apply (finalize fused) ----------------
__global__ void bn_apply_kernel(const float* __restrict__ xd,
                                const float* __restrict__ B1,
                                const float* __restrict__ B2,
                                const float* __restrict__ dg,
                                const float* __restrict__ db,
                                float* __restrict__ out)
{
    size_t i4 = (size_t)blockIdx.x * 256 + threadIdx.x;
    const size_t total4 = (size_t)NN * CO * LO / 4;
    if (i4 >= total4) return;
    float4 v = ((const float4*)xd)[i4];
    int o = (int)((i4 * 4 / LO) & (CO - 1));
    const float cnt = (float)NN * LO;
    float mu = B1[o] / cnt;
    float var = B2[o] / cnt - mu * mu;
    float sc = dg[o] * rsqrtf(var + 1e-5f);
    float sh = db[o] - mu * sc;
    float4 r;
    r.x = mishf(v.x * sc + sh);
    r.y = mishf(v.y * sc + sh);
    r.z = mishf(v.z * sc + sh);
    r.w = mishf(v.w * sc + sh);
    ((float4*)out)[i4] = r;
}

// ---------------- launch ----------------
extern "C" void kernel_launch(void* const* d_in, const int* in_sizes, int n_in,
                              void* d_out, int out_size)
{
    const float* x        = (const float*)d_in[0];
    const float* t        = (const float*)d_in[1];
    const float* l1_k5    = (const float*)d_in[2];
    const float* l1_k3    = (const float*)d_in[3];
    const float* l1_k1    = (const float*)d_in[4];
    const float* l1_a3    = (const float*)d_in[5];
    const float* l1_a5    = (const float*)d_in[6];
    const float* l1_gw    = (const float*)d_in[7];
    const float* l1_gb    = (const float*)d_in[8];
    const float* l1_gamma = (const float*)d_in[9];
    const float* l1_beta  = (const float*)d_in[10];
    const float* l2_k5    = (const float*)d_in[11];
    const float* l2_k3    = (const float*)d_in[12];
    const float* l2_k1    = (const float*)d_in[13];
    const float* l2_a3    = (const float*)d_in[14];
    const float* l2_a5    = (const float*)d_in[15];
    const float* l2_gw    = (const float*)d_in[16];
    const float* l2_gb    = (const float*)d_in[17];
    const float* l2_gamma = (const float*)d_in[18];
    const float* l2_beta  = (const float*)d_in[19];
    const float* dw       = (const float*)d_in[20];
    const float* dg       = (const float*)d_in[21];
    const float* db       = (const float*)d_in[22];

    float* out      = (float*)d_out;
    float* out_xd   = out;
    float* out_skip = out + (size_t)NN * CO * LO;

    __half *xh, *hh, *ssh, *ybuf, *w1h, *w2h, *wdh;
    float *xdbuf, *s1, *s2, *b1, *b2;
    cudaGetSymbolAddress((void**)&xh, g_xh);
    cudaGetSymbolAddress((void**)&hh, g_hh);
    cudaGetSymbolAddress((void**)&ssh, g_ssh);
    cudaGetSymbolAddress((void**)&ybuf, g_y);
    cudaGetSymbolAddress((void**)&w1h, g_w1h);
    cudaGetSymbolAddress((void**)&w2h, g_w2h);
    cudaGetSymbolAddress((void**)&wdh, g_wdh);
    cudaGetSymbolAddress((void**)&xdbuf, g_xd);
    cudaGetSymbolAddress((void**)&s1, g_s1);
    cudaGetSymbolAddress((void**)&s2, g_s2);
    cudaGetSymbolAddress((void**)&b1, g_b1);
    cudaGetSymbolAddress((void**)&b2, g_b2);

    // smem: XT + 2 W buffers
    const int SM1 = 260 * 144 + 2 * 9216;   // 55872   (NT=256)
    const int SM2 = 260 * 272 + 2 * 9216;   // 89152   (NT=256)
    const int SMD = 256 * 272 + 2 * 9216;   // 88064   (NT=128, RS=2)
    cudaFuncSetAttribute((const void*)mma_conv<64, 5, 1, 4, 256, true, __half>,
                         cudaFuncAttributeMaxDynamicSharedMemorySize, SM1);
    cudaFuncSetAttribute((const void*)mma_conv<128, 5, 1, 4, 256, true, __half>,
                         cudaFuncAttributeMaxDynamicSharedMemorySize, SM2);
    cudaFuncSetAttribute((const void*)mma_conv<128, 2, 2, 0, 128, false, float>,
                         cudaFuncAttributeMaxDynamicSharedMemorySize, SMD);

    // x -> fp16
    {
        size_t c4 = (size_t)NN * LL * CI1 / 4;
        split_x_kernel<<<(int)((c4 + 255) / 256), 256>>>(x, xh, c4);
    }

    // layer 1
    gate_weights_kernel<<<dim3(NN, CI1 / 64, 4), 512>>>(t, l1_gw, l1_gb, l1_k5, l1_k3, l1_k1,
                                                        l1_a3, l1_a5, w1h, s1, s2, CI1);
    mma_conv<64, 5, 1, 4, 256, true, __half><<<dim3(LL / 256, NN, 2), 256, SM1>>>(
        xh, w1h, ybuf, s1, s2, (size_t)LL * CI1, (size_t)5 * 1 * CO * 64, LL);
    norm_transpose_kernel<<<dim3(LL / 32, NN), 256>>>(ybuf, s1, s2, l1_gamma, l1_beta,
                                                      nullptr, hh);

    // layer 2
    gate_weights_kernel<<<dim3(NN, CO / 64, 4), 512>>>(t, l2_gw, l2_gb, l2_k5, l2_k3, l2_k1,
                                                       l2_a3, l2_a5, w2h, s1, s2, CO);
    mma_conv<128, 5, 1, 4, 256, true, __half><<<dim3(LL / 256, NN, 2), 256, SM2>>>(
        hh, w2h, ybuf, s1, s2, (size_t)LL * CO, (size_t)5 * 2 * CO * 64, LL);
    norm_transpose_kernel<<<dim3(LL / 32, NN), 256>>>(ybuf, s1, s2, l2_gamma, l2_beta,
                                                      out_skip, ssh);

    // downsample + BN + mish
    split_dw_kernel<<<(CO * 256 + 255) / 256, 256>>>(dw, wdh, b1, b2);
    mma_conv<128, 2, 2, 0, 128, false, float><<<dim3(LO / 128, NN, 2), 256, SMD>>>(
        ssh, wdh, xdbuf, b1, b2, (size_t)LL * CO, 0, LO);
    bn_apply_kernel<<<(int)(((size_t)NN * CO * LO / 4 + 255) / 256), 256>>>(
        xdbuf, b1, b2, dg, db, out_xd);
}

// round 13
// speedup vs baseline: 1.9384x; 1.1455x over previous
#include <cuda_runtime.h>
#include <cuda_fp16.h>
#include <math.h>
#include <stdint.h>

#define NN 32
#define LL 8192
#define CO 128
#define CI1 64
#define TT 10
#define LO 4096

// ---------------- scratch (__device__ globals; no allocation) ----------------
__device__ __align__(128) __half g_xh[(size_t)NN * LL * CI1];
__device__ __align__(128) __half g_hh[(size_t)NN * LL * CO];
__device__ __align__(128) __half g_ssh[(size_t)NN * LL * CO];
__device__ __align__(128) __half g_y[(size_t)NN * CO * LL];
__device__ __align__(128) float g_xd[(size_t)NN * CO * LO];
__device__ __align__(128) __half g_w1h[(size_t)NN * 5 * 1 * CO * 64];
__device__ __align__(128) __half g_w2h[(size_t)NN * 5 * 2 * CO * 64];
__device__ __align__(128) __half g_wdh[4 * CO * 64];
__device__ float g_s1[NN * CO];
__device__ float g_s2[NN * CO];
__device__ float g_b1[CO];
__device__ float g_b2[CO];

// ---------------- small device helpers ----------------
// Fast mish: x * tanh(softplus(x)) with tanh(ln(1+e)) = ((1+e)^2-1)/((1+e)^2+1).
// One MUFU.EX2 + one fast divide. x>8 -> x (rel err ~2e-7); x<-80 -> exactly 0.
__device__ __forceinline__ float mishf(float v) {
    if (v > 8.f) return v;
    float e = __expf(v);
    float t = 1.f + e;
    float t2 = t * t;
    return v * __fdividef(t2 - 1.f, t2 + 1.f);
}
__device__ __forceinline__ uint32_t smem_u32(const void* p) {
    uint32_t a;
    asm("{ .reg .u64 t; cvta.to.shared.u64 t, %1; cvt.u32.u64 %0, t; }" : "=r"(a) : "l"(p));
    return a;
}
__device__ __forceinline__ void cp16(uint32_t dst, const void* src) {
    asm volatile("cp.async.cg.shared.global [%0], [%1], 16;" :: "r"(dst), "l"(src));
}
__device__ __forceinline__ void cp_commit() {
    asm volatile("cp.async.commit_group;" ::: "memory");
}
template <int N>
__device__ __forceinline__ void cp_wait() {
    asm volatile("cp.async.wait_group %0;" :: "n"(N) : "memory");
}
__device__ __forceinline__ void ldsm4(uint32_t* r, uint32_t addr) {
    asm volatile("ldmatrix.sync.aligned.m8n8.x4.shared.b16 {%0,%1,%2,%3}, [%4];"
                 : "=r"(r[0]), "=r"(r[1]), "=r"(r[2]), "=r"(r[3]) : "r"(addr));
}
__device__ __forceinline__ void mma_f16(float* d, const uint32_t* a, const uint32_t* b) {
    asm volatile("mma.sync.aligned.m16n8k16.row.col.f32.f16.f16.f32 "
                 "{%0,%1,%2,%3}, {%4,%5,%6,%7}, {%8,%9}, {%0,%1,%2,%3};"
                 : "+f"(d[0]), "+f"(d[1]), "+f"(d[2]), "+f"(d[3])
                 : "r"(a[0]), "r"(a[1]), "r"(a[2]), "r"(a[3]), "r"(b[0]), "r"(b[1]));
}

// ============================================================================
// Conv-as-GEMM, warp-level fp16 MMA (single fp16 W).
// CTA = 256 threads (8 warps, 2x4); tile M=64 (o-half, blockIdx.z) x NT.
// NT=256 for conv1/2, NT=128 for downsample. Output YT = __half or float.
// Fused per-(n,o)/per-o sum/sumsq stats via shuffle + atomics.
// ============================================================================
template <int CI, int NSHIFT, int RS, int HALO, int NT, bool PER_N_STATS, typename YT>
__global__ void __launch_bounds__(256, 2)
mma_conv(const __half* __restrict__ X,
         const __half* __restrict__ Wh,
         YT* __restrict__ Y, float* __restrict__ S1, float* __restrict__ S2,
         size_t x_nstride, size_t w_nstride, int outL)
{
    constexpr int HF = CI / 64;
    constexpr int P = NSHIFT * HF;
    constexpr int XR = NT * RS + HALO;
    constexpr int XPITCH = CI * 2 + 16;      // bytes; row step ≡ 4 banks (mod 32)
    constexpr int WPITCH = 144;
    constexpr int WCH = 64 * WPITCH;
    constexpr int XT = XR * XPITCH;
    constexpr int SEGR = CI / 8;
    constexpr int NB = NT / 64;
    constexpr int NFR = 2 * NB;

    extern __shared__ char sm[];
    const uint32_t base = smem_u32(sm);
    const uint32_t x_s = base;
    const uint32_t w_s = base + XT;

    const int tid = threadIdx.x;
    const int n = blockIdx.y;
    const int l0 = blockIdx.x * NT;
    const int o_base = blockIdx.z * 64;

    if (HALO > 0 && blockIdx.x == 0) {
        const uint4 z = make_uint4(0, 0, 0, 0);
        for (int s = tid; s < HALO * SEGR; s += 256) {
            int r = s / SEGR, c = s % SEGR;
            *(uint4*)(sm + r * XPITCH + c * 16) = z;
        }
    }
    {   // X tile
        const __half* gx = X + (size_t)n * x_nstride;
        for (int s = tid; s < XR * SEGR; s += 256) {
            int r = s / SEGR, c = s % SEGR;
            long l = (long)l0 * RS - HALO + r;
            if (l >= 0)
                cp16(x_s + r * XPITCH + c * 16, gx + (size_t)l * CI + (size_t)c * 8);
        }
    }
    auto load_w = [&](int piece, int buf) {
        const __half* ph = Wh + (size_t)n * w_nstride + (size_t)piece * (CO * 64)
                           + (size_t)o_base * 64;
        uint32_t dst = w_s + (uint32_t)buf * WCH;
        for (int s = tid; s < 512; s += 256) {
            int r = s >> 3, c = s & 7;
            cp16(dst + r * WPITCH + c * 16, ph + r * 64 + c * 8);
        }
        cp_commit();
    };
    load_w(0, 0);

    const int warp = tid >> 5, lane = tid & 31;
    const int o0w = (warp >> 2) * 32;
    const int n0w = (warp & 3) * (NT / 4);
    const int a_row = (lane & 7) + ((lane >> 3) & 1) * 8;
    const int a_csh = (lane >> 4) * 8;
    const int b_jj = (lane & 7) + ((lane >> 4) << 3);
    const int b_csh = ((lane >> 3) & 1) * 8;

    float acc[2][NFR][4];
#pragma unroll
    for (int mi = 0; mi < 2; mi++)
#pragma unroll
        for (int nf = 0; nf < NFR; nf++)
#pragma unroll
            for (int q = 0; q < 4; q++) acc[mi][nf][q] = 0.f;

    for (int p = 0; p < P; p++) {
        cp_wait<0>();
        __syncthreads();   // readers of buffer (p+1)&1 (= piece p-1) are done
        if (p + 1 < P) load_w(p + 1, (p + 1) & 1);

        const int k = p / HF, hf = p % HF;
        const uint32_t wh_b = w_s + (uint32_t)(p & 1) * WCH;

#pragma unroll
        for (int i16 = 0; i16 < 4; i16++) {
            const int i0 = i16 * 16;
            uint32_t Ah[2][4];
#pragma unroll
            for (int mi = 0; mi < 2; mi++) {
                uint32_t ao = (uint32_t)((o0w + a_row + mi * 16) * WPITCH + (i0 + a_csh) * 2);
                ldsm4(Ah[mi], wh_b + ao);
            }
            const int xcol = (hf * 64 + i0 + b_csh) * 2;
#pragma unroll
            for (int nb = 0; nb < NB; nb++) {
                uint32_t B[4];
                uint32_t xo = (uint32_t)((RS * (n0w + nb * 16 + b_jj) + k) * XPITCH + xcol);
                ldsm4(B, x_s + xo);
#pragma unroll
                for (int mi = 0; mi < 2; mi++)
#pragma unroll
                    for (int hl = 0; hl < 2; hl++)
                        mma_f16(acc[mi][nb * 2 + hl], Ah[mi], &B[hl * 2]);
            }
        }
    }

    // ---------------- epilogue: store + fused stats ----------------
    const int g = lane >> 2, tg = lane & 3;
#pragma unroll
    for (int mi = 0; mi < 2; mi++) {
        const int o = o_base + o0w + mi * 16 + g;
        YT* row0 = Y + ((size_t)(n * CO + o)) * outL + l0 + n0w;
        YT* row1 = row0 + (size_t)8 * outL;
#pragma unroll
        for (int nf = 0; nf < NFR; nf++) {
            int c = nf * 8 + tg * 2;
            if (sizeof(YT) == 2) {
                *(__half2*)((__half*)row0 + c) = __floats2half2_rn(acc[mi][nf][0], acc[mi][nf][1]);
                *(__half2*)((__half*)row1 + c) = __floats2half2_rn(acc[mi][nf][2], acc[mi][nf][3]);
            } else {
                *(float2*)((float*)row0 + c) = make_float2(acc[mi][nf][0], acc[mi][nf][1]);
                *(float2*)((float*)row1 + c) = make_float2(acc[mi][nf][2], acc[mi][nf][3]);
            }
        }
    }
    float ts[4], tq[4];
#pragma unroll
    for (int r = 0; r < 4; r++) { ts[r] = 0.f; tq[r] = 0.f; }
#pragma unroll
    for (int mi = 0; mi < 2; mi++)
#pragma unroll
        for (int nf = 0; nf < NFR; nf++) {
            float a0 = acc[mi][nf][0], a1 = acc[mi][nf][1];
            float a2 = acc[mi][nf][2], a3 = acc[mi][nf][3];
            ts[2 * mi]     += a0 + a1;  tq[2 * mi]     += a0 * a0 + a1 * a1;
            ts[2 * mi + 1] += a2 + a3;  tq[2 * mi + 1] += a2 * a2 + a3 * a3;
        }
#pragma unroll
    for (int r = 0; r < 4; r++) {
        ts[r] += __shfl_xor_sync(0xffffffffu, ts[r], 1);
        ts[r] += __shfl_xor_sync(0xffffffffu, ts[r], 2);
        tq[r] += __shfl_xor_sync(0xffffffffu, tq[r], 1);
        tq[r] += __shfl_xor_sync(0xffffffffu, tq[r], 2);
    }
    if (tg == 0) {
        const int sbase = PER_N_STATS ? n * CO : 0;
#pragma unroll
        for (int r = 0; r < 4; r++) {
            int o = o_base + o0w + (r >> 1) * 16 + g + (r & 1) * 8;
            atomicAdd(&S1[sbase + o], ts[r]);
            atomicAdd(&S2[sbase + o], tq[r]);
        }
    }
}

// ---------------- fp32 -> fp16 ----------------
__global__ void split_x_kernel(const float* __restrict__ src,
                               __half* __restrict__ hi, size_t count4)
{
    size_t i = (size_t)blockIdx.x * 256 + threadIdx.x;
    if (i >= count4) return;
    float4 v = ((const float4*)src)[i];
    ((__half2*)hi)[2 * i]     = __floats2half2_rn(v.x, v.y);
    ((__half2*)hi)[2 * i + 1] = __floats2half2_rn(v.z, v.w);
}

// ---------------- gate + per-sample weights (fp16) ----------------
__global__ void __launch_bounds__(512)
gate_weights_kernel(const float* __restrict__ t,
                    const float* __restrict__ gw,
                    const float* __restrict__ gb,
                    const float* __restrict__ k5,
                    const float* __restrict__ k3,
                    const float* __restrict__ k1,
                    const float* __restrict__ a3,
                    const float* __restrict__ a5,
                    __half* __restrict__ wh,
                    float* __restrict__ S1, float* __restrict__ S2,
                    int CI)
{
    const int n = blockIdx.x;
    const int hf = blockIdx.y;
    const int HF = gridDim.y;
    const int oc = blockIdx.z;
    const int tid = threadIdx.x;

    __shared__ float gs[5][128];
    if (tid < 128) {
        const int o = tid;
        if (blockIdx.y == 0 && blockIdx.z == 0) {
            S1[n * CO + o] = 0.f;
            S2[n * CO + o] = 0.f;
        }
        float tv[TT];
#pragma unroll
        for (int j = 0; j < TT; j++) tv[j] = t[n * TT + j];
        float g[5];
        float mx = -1e30f;
#pragma unroll
        for (int e = 0; e < 5; e++) {
            float s = gb[e * CO + o];
            const float* gwr = gw + (size_t)(e * CO + o) * TT;
#pragma unroll
            for (int j = 0; j < TT; j++) s += tv[j] * gwr[j];
            g[e] = s;
            mx = fmaxf(mx, s);
        }
        float den = 0.f;
#pragma unroll
        for (int e = 0; e < 5; e++) { g[e] = expf(g[e] - mx); den += g[e]; }
        float inv = 1.f / den;
        gs[0][o] = g[0] * inv;
        gs[1][o] = g[1] * inv;
        gs[2][o] = g[2] * inv;
        gs[3][o] = g[3] * inv * (1.f / 3.f);
        gs[4][o] = g[4] * inv * 0.2f;
    }
    __syncthreads();

    const int og = tid >> 6;
    const int ii = tid & 63;
    const int i = hf * 64 + ii;
    const size_t kstride = (size_t)HF * 128 * 64;

#pragma unroll
    for (int oj = 0; oj < 4; oj++) {
        const int o = oc * 32 + oj * 8 + og;
        const float g0 = gs[0][o], g1 = gs[1][o], g2 = gs[2][o];
        const float g3v = gs[3][o], g4v = gs[4][o];
        const int oi = o * CI + i;
        const float* p5 = k5 + (size_t)oi * 5;
        const float* p3 = k3 + (size_t)oi * 3;
        const float bse = g4v * a5[oi];
        const float c3v = g3v * a3[oi];
        float wv[5];
        wv[0] = g0 * p5[0] + bse;
        wv[1] = g0 * p5[1] + bse;
        wv[2] = g0 * p5[2] + g1 * p3[0] + c3v + bse;
        wv[3] = g0 * p5[3] + g1 * p3[1] + c3v + bse;
        wv[4] = g0 * p5[4] + g1 * p3[2] + c3v + g2 * k1[oi] + bse;
        const size_t idx0 = (((size_t)n * 5 * HF + hf) * 128 + o) * 64 + ii;
#pragma unroll
        for (int k = 0; k < 5; k++)
            wh[idx0 + k * kstride] = __float2half_rn(wv[k]);
    }
}

// ---------------- downsample weight reorder (+ zero bn accums) -------
__global__ void split_dw_kernel(const float* __restrict__ dw,
                                __half* __restrict__ wdh,
                                float* __restrict__ B1, float* __restrict__ B2)
{
    int idx = blockIdx.x * 256 + threadIdx.x;
    if (blockIdx.x == 0) {
        if (threadIdx.x < CO) B1[threadIdx.x] = 0.f;
        else B2[threadIdx.x - CO] = 0.f;
    }
    if (idx >= CO * 256) return;
    int o = idx >> 8, r = idx & 255;
    int kk = r >> 7, ifull = r & 127;
    float v = dw[(size_t)o * 256 + ifull * 2 + kk];
    size_t out = (((size_t)kk * 2 + (ifull >> 6)) * 128 + o) * 64 + (ifull & 63);
    wdh[out] = __float2half_rn(v);
}

// ---------------- norm + mish + transpose (inorm finalize fused) ------------
__global__ void norm_transpose_kernel(const __half* __restrict__ y,
                                      const float* __restrict__ S1,
                                      const float* __restrict__ S2,
                                      const float* __restrict__ gamma,
                                      const float* __restrict__ beta,
                                      float* __restrict__ out_full,
                                      __half* __restrict__ out_hi)
{
    __shared__ float tile[CO][33];
    __shared__ float sc[CO], sh[CO];
    int n = blockIdx.y, l0 = blockIdx.x * 32;
    int tid = threadIdx.x;
    if (tid < CO) {
        int no = n * CO + tid;
        float mu = S1[no] * (1.f / LL);
        float var = S2[no] * (1.f / LL) - mu * mu;
        float s = gamma[tid] * rsqrtf(var + 1e-5f);
        sc[tid] = s;
        sh[tid] = beta[tid] - mu * s;
    }
    __syncthreads();
    int lt = tid & 31, ob = tid >> 5;
#pragma unroll
    for (int r = 0; r < 16; r++) {
        int o = ob + 8 * r;
        float v = __half2float(y[((size_t)(n * CO + o)) * LL + l0 + lt]);
        tile[o][lt] = mishf(v * sc[o] + sh[o]);
    }
    __syncthreads();
    int oc = tid & 127, lb = tid >> 7;
#pragma unroll
    for (int ly = lb; ly < 32; ly += 2) {
        size_t idx = ((size_t)n * LL + l0 + ly) * CO + oc;
        float v = tile[oc][ly];
        if (out_full) out_full[idx] = v;
        out_hi[idx] = __float2half_rn(v);
    }
}

// ---------------- batch-norm apply (finalize fused) ----------------
__global__ void bn_apply_kernel(const float* __restrict__ xd,
                                const float* __restrict__ B1,
                                const float* __restrict__ B2,
                                const float* __restrict__ dg,
                                const float* __restrict__ db,
                                float* __restrict__ out)
{
    size_t i4 = (size_t)blockIdx.x * 256 + threadIdx.x;
    const size_t total4 = (size_t)NN * CO * LO / 4;
    if (i4 >= total4) return;
    float4 v = ((const float4*)xd)[i4];
    int o = (int)((i4 * 4 / LO) & (CO - 1));
    const float cnt = (float)NN * LO;
    float mu = B1[o] / cnt;
    float var = B2[o] / cnt - mu * mu;
    float sc = dg[o] * rsqrtf(var + 1e-5f);
    float sh = db[o] - mu * sc;
    float4 r;
    r.x = mishf(v.x * sc + sh);
    r.y = mishf(v.y * sc + sh);
    r.z = mishf(v.z * sc + sh);
    r.w = mishf(v.w * sc + sh);
    ((float4*)out)[i4] = r;
}

// ---------------- launch ----------------
extern "C" void kernel_launch(void* const* d_in, const int* in_sizes, int n_in,
                              void* d_out, int out_size)
{
    const float* x        = (const float*)d_in[0];
    const float* t        = (const float*)d_in[1];
    const float* l1_k5    = (const float*)d_in[2];
    const float* l1_k3    = (const float*)d_in[3];
    const float* l1_k1    = (const float*)d_in[4];
    const float* l1_a3    = (const float*)d_in[5];
    const float* l1_a5    = (const float*)d_in[6];
    const float* l1_gw    = (const float*)d_in[7];
    const float* l1_gb    = (const float*)d_in[8];
    const float* l1_gamma = (const float*)d_in[9];
    const float* l1_beta  = (const float*)d_in[10];
    const float* l2_k5    = (const float*)d_in[11];
    const float* l2_k3    = (const float*)d_in[12];
    const float* l2_k1    = (const float*)d_in[13];
    const float* l2_a3    = (const float*)d_in[14];
    const float* l2_a5    = (const float*)d_in[15];
    const float* l2_gw    = (const float*)d_in[16];
    const float* l2_gb    = (const float*)d_in[17];
    const float* l2_gamma = (const float*)d_in[18];
    const float* l2_beta  = (const float*)d_in[19];
    const float* dw       = (const float*)d_in[20];
    const float* dg       = (const float*)d_in[21];
    const float* db       = (const float*)d_in[22];

    float* out      = (float*)d_out;
    float* out_xd   = out;
    float* out_skip = out + (size_t)NN * CO * LO;

    __half *xh, *hh, *ssh, *ybuf, *w1h, *w2h, *wdh;
    float *xdbuf, *s1, *s2, *b1, *b2;
    cudaGetSymbolAddress((void**)&xh, g_xh);
    cudaGetSymbolAddress((void**)&hh, g_hh);
    cudaGetSymbolAddress((void**)&ssh, g_ssh);
    cudaGetSymbolAddress((void**)&ybuf, g_y);
    cudaGetSymbolAddress((void**)&w1h, g_w1h);
    cudaGetSymbolAddress((void**)&w2h, g_w2h);
    cudaGetSymbolAddress((void**)&wdh, g_wdh);
    cudaGetSymbolAddress((void**)&xdbuf, g_xd);
    cudaGetSymbolAddress((void**)&s1, g_s1);
    cudaGetSymbolAddress((void**)&s2, g_s2);
    cudaGetSymbolAddress((void**)&b1, g_b1);
    cudaGetSymbolAddress((void**)&b2, g_b2);

    // smem: XT + 2 W buffers
    const int SM1 = 260 * 144 + 2 * 9216;   // 55872   (NT=256)
    const int SM2 = 260 * 272 + 2 * 9216;   // 89152   (NT=256)
    const int SMD = 256 * 272 + 2 * 9216;   // 88064   (NT=128, RS=2)
    cudaFuncSetAttribute((const void*)mma_conv<64, 5, 1, 4, 256, true, __half>,
                         cudaFuncAttributeMaxDynamicSharedMemorySize, SM1);
    cudaFuncSetAttribute((const void*)mma_conv<128, 5, 1, 4, 256, true, __half>,
                         cudaFuncAttributeMaxDynamicSharedMemorySize, SM2);
    cudaFuncSetAttribute((const void*)mma_conv<128, 2, 2, 0, 128, false, float>,
                         cudaFuncAttributeMaxDynamicSharedMemorySize, SMD);

    // x -> fp16
    {
        size_t c4 = (size_t)NN * LL * CI1 / 4;
        split_x_kernel<<<(int)((c4 + 255) / 256), 256>>>(x, xh, c4);
    }

    // layer 1
    gate_weights_kernel<<<dim3(NN, CI1 / 64, 4), 512>>>(t, l1_gw, l1_gb, l1_k5, l1_k3, l1_k1,
                                                        l1_a3, l1_a5, w1h, s1, s2, CI1);
    mma_conv<64, 5, 1, 4, 256, true, __half><<<dim3(LL / 256, NN, 2), 256, SM1>>>(
        xh, w1h, ybuf, s1, s2, (size_t)LL * CI1, (size_t)5 * 1 * CO * 64, LL);
    norm_transpose_kernel<<<dim3(LL / 32, NN), 256>>>(ybuf, s1, s2, l1_gamma, l1_beta,
                                                      nullptr, hh);

    // layer 2
    gate_weights_kernel<<<dim3(NN, CO / 64, 4), 512>>>(t, l2_gw, l2_gb, l2_k5, l2_k3, l2_k1,
                                                       l2_a3, l2_a5, w2h, s1, s2, CO);
    mma_conv<128, 5, 1, 4, 256, true, __half><<<dim3(LL / 256, NN, 2), 256, SM2>>>(
        hh, w2h, ybuf, s1, s2, (size_t)LL * CO, (size_t)5 * 2 * CO * 64, LL);
    norm_transpose_kernel<<<dim3(LL / 32, NN), 256>>>(ybuf, s1, s2, l2_gamma, l2_beta,
                                                      out_skip, ssh);

    // downsample + BN + mish
    split_dw_kernel<<<(CO * 256 + 255) / 256, 256>>>(dw, wdh, b1, b2);
    mma_conv<128, 2, 2, 0, 128, false, float><<<dim3(LO / 128, NN, 2), 256, SMD>>>(
        ssh, wdh, xdbuf, b1, b2, (size_t)LL * CO, 0, LO);
    bn_apply_kernel<<<(int)(((size_t)NN * CO * LO / 4 + 255) / 256), 256>>>(
        xdbuf, b1, b2, dg, db, out_xd);
}